// round 7
// baseline (speedup 1.0000x reference)
#include <cuda_runtime.h>
#include <cuda_bf16.h>
#include <math.h>
#include <stdint.h>

// ---------------------------------------------------------------------------
// GraphAE on GB300 (sm_103 plain target -> mma.sync tensor path).
// pseudo == 0 => only spline weight k=0 contributes.
// 3-product compensated bf16 MMA (fp32 accum) == fp32-accurate GEMMs.
// Pipeline (7 launches):
//   prep -> hist -> scan1 -> scan3(self-zeroing) -> place
//   -> FUSED1[gather(x)+G1+G2 -> hWr planes]
//   -> FUSED2[gather(hWr)+G3+G4 -> out]
// ---------------------------------------------------------------------------

#define NNODES 50000
#define NEDGES 800000
#define NB_SCAN 49

// ------------------------- scratch (static device) -------------------------
__device__ int   g_cnt[NNODES];        // zero-init (BSS); scan3 restores zero
__device__ int   g_rowptr[NNODES + 1];
__device__ int   g_cursor[NNODES];
__device__ int   g_csr[NEDGES];
__device__ float g_invdeg[NNODES];
__device__ int   g_scantmp[NNODES];
__device__ int   g_bsum[NB_SCAN];

// inter-stage activation planes (bf16 hi/lo): hWr = [h@W2 | h@root2 + b2]
__device__ __nv_bfloat16 g_wh[(size_t)NNODES * 128], g_wl[(size_t)NNODES * 128];

// bf16 hi/lo split weights, natural [k][n] row-major
__device__ __nv_bfloat16 g_B1h[128 * 256], g_B1l[128 * 256];
__device__ __nv_bfloat16 g_B2h[256 * 128], g_B2l[256 * 128];
__device__ __nv_bfloat16 g_D1h[64 * 256],  g_D1l[64 * 256];
__device__ __nv_bfloat16 g_D2h[256 * 64],  g_D2l[256 * 64];
__device__ float g_b2c[128];                   // [0 | conv2_b]

// ------------------------------ helpers ------------------------------------
__device__ __forceinline__ uint32_t smem_u32(const void* p) {
    uint32_t a;
    asm("{ .reg .u64 t; cvta.to.shared.u64 t, %1; cvt.u32.u64 %0, t; }"
        : "=r"(a) : "l"(p));
    return a;
}
__device__ __forceinline__ void ldsm_x4(uint32_t* r, uint32_t addr) {
    asm volatile("ldmatrix.sync.aligned.m8n8.x4.shared.b16 {%0,%1,%2,%3}, [%4];"
                 : "=r"(r[0]), "=r"(r[1]), "=r"(r[2]), "=r"(r[3]) : "r"(addr));
}
__device__ __forceinline__ void ldsm_x4t(uint32_t* r, uint32_t addr) {
    asm volatile("ldmatrix.sync.aligned.m8n8.x4.trans.shared.b16 {%0,%1,%2,%3}, [%4];"
                 : "=r"(r[0]), "=r"(r[1]), "=r"(r[2]), "=r"(r[3]) : "r"(addr));
}
__device__ __forceinline__ void mma_bf16(float* d, const uint32_t* a,
                                         uint32_t b0, uint32_t b1) {
    asm volatile("mma.sync.aligned.m16n8k16.row.col.f32.bf16.bf16.f32 "
                 "{%0,%1,%2,%3}, {%4,%5,%6,%7}, {%8,%9}, {%0,%1,%2,%3};"
                 : "+f"(d[0]), "+f"(d[1]), "+f"(d[2]), "+f"(d[3])
                 : "r"(a[0]), "r"(a[1]), "r"(a[2]), "r"(a[3]), "r"(b0), "r"(b1));
}
__device__ __forceinline__ void cpa16(uint32_t dst, const void* src) {
    asm volatile("cp.async.cg.shared.global [%0], [%1], 16;"
                 :: "r"(dst), "l"(src));
}
#define CP_COMMIT() asm volatile("cp.async.commit_group;" ::: "memory")
#define CP_WAIT0()  asm volatile("cp.async.wait_group 0;" ::: "memory")

__device__ __forceinline__ void split1(float v, uint16_t& h, uint16_t& l) {
    __nv_bfloat16 hb = __float2bfloat16_rn(v);
    float r = v - __bfloat162float(hb);
    __nv_bfloat16 lb = __float2bfloat16_rn(r);
    h = __bfloat16_as_ushort(hb);
    l = __bfloat16_as_ushort(lb);
}
__device__ __forceinline__ void split_pair(float a, float b, uint32_t& hp, uint32_t& lp) {
    uint16_t h0, l0, h1, l1;
    split1(a, h0, l0); split1(b, h1, l1);
    hp = (uint32_t)h0 | ((uint32_t)h1 << 16);
    lp = (uint32_t)l0 | ((uint32_t)l1 << 16);
}
__device__ __forceinline__ float2 bf2f(uint32_t u) {
    __nv_bfloat162 t = *reinterpret_cast<__nv_bfloat162*>(&u);
    return __bfloat1622float2(t);
}

// ------------------------------ weight prep --------------------------------
__global__ void prep_k(const float* __restrict__ c1W, const float* __restrict__ c1r,
                       const float* __restrict__ c2W, const float* __restrict__ c2r,
                       const float* __restrict__ c2b,
                       const float* __restrict__ dw1, const float* __restrict__ dw2) {
    int i = blockIdx.x * blockDim.x + threadIdx.x;
    uint16_t h, l;
    if (i < 128 * 256) {  // B1 [k=128][n=256]
        int k = i >> 8, n = i & 255;
        float v = (k < 64) ? c1W[k * 256 + n] : c1r[(k - 64) * 256 + n];
        split1(v, h, l);
        g_B1h[i] = __ushort_as_bfloat16(h); g_B1l[i] = __ushort_as_bfloat16(l);
    }
    if (i < 256 * 128) {  // B2 [k=256][n=128]
        int k = i >> 7, n = i & 127;
        float v = (n < 64) ? c2W[k * 64 + n] : c2r[k * 64 + (n - 64)];
        split1(v, h, l);
        g_B2h[i] = __ushort_as_bfloat16(h); g_B2l[i] = __ushort_as_bfloat16(l);
    }
    if (i < 64 * 256) {   // D1 [k=64][n=256]
        split1(dw1[i], h, l);
        g_D1h[i] = __ushort_as_bfloat16(h); g_D1l[i] = __ushort_as_bfloat16(l);
    }
    if (i < 256 * 64) {   // D2 [k=256][n=64]
        split1(dw2[i], h, l);
        g_D2h[i] = __ushort_as_bfloat16(h); g_D2l[i] = __ushort_as_bfloat16(l);
    }
    if (i < 128) g_b2c[i] = (i < 64) ? 0.0f : c2b[i - 64];
}

// ------------------------------- CSR build ---------------------------------
__global__ void hist_k(const int* __restrict__ ei) {
    int e = blockIdx.x * blockDim.x + threadIdx.x;
    if (e < NEDGES) atomicAdd(&g_cnt[ei[NEDGES + e]], 1);
}

__global__ void scan1_k() {
    __shared__ int sh[1024];
    int i = blockIdx.x * 1024 + threadIdx.x;
    int v = (i < NNODES) ? g_cnt[i] : 0;
    sh[threadIdx.x] = v;
    __syncthreads();
    #pragma unroll
    for (int off = 1; off < 1024; off <<= 1) {
        int t = (threadIdx.x >= off) ? sh[threadIdx.x - off] : 0;
        __syncthreads();
        sh[threadIdx.x] += t;
        __syncthreads();
    }
    if (i < NNODES) g_scantmp[i] = sh[threadIdx.x];
    if (threadIdx.x == 1023) g_bsum[blockIdx.x] = sh[1023];
}

// folds the 49-block-sum scan in (redundant per block); re-zeroes g_cnt so
// the next graph replay starts from a clean histogram (no memset launch).
__global__ void scan3_k() {
    __shared__ int sb[64], so[64];
    int tid = threadIdx.x;
    if (tid < 64) {
        int v = (tid < NB_SCAN) ? g_bsum[tid] : 0;
        so[tid] = v;
        sb[tid] = v;
    }
    __syncthreads();
    #pragma unroll
    for (int off = 1; off < 64; off <<= 1) {
        int t = 0;
        if (tid < 64 && tid >= off) t = sb[tid - off];
        __syncthreads();
        if (tid < 64) sb[tid] += t;
        __syncthreads();
    }
    int i = blockIdx.x * blockDim.x + tid;
    if (i < NNODES) {
        int b = i >> 10;
        int boff = sb[b] - so[b];
        int incl = g_scantmp[i] + boff;
        int c = g_cnt[i];
        int start = incl - c;
        g_rowptr[i] = start;
        g_cursor[i] = start;
        g_invdeg[i] = 1.0f / fmaxf((float)c, 1.0f);
        g_cnt[i] = 0;                       // restore for next launch
        if (i == NNODES - 1) g_rowptr[NNODES] = incl;
    }
}

__global__ void place_k(const int* __restrict__ ei) {
    int e = blockIdx.x * blockDim.x + threadIdx.x;
    if (e < NEDGES) {
        int d = ei[NEDGES + e];
        int p = atomicAdd(&g_cursor[d], 1);
        g_csr[p] = ei[e];  // src
    }
}

// --------------- fused gather + two-GEMM kernel (64-row tile) --------------
// Phase0: gather this CTA's 64 node rows (CSR mean-aggregation) -> A smem
//         planes (bf16 hi/lo).  MODE 1: A=[agg(x)|x] K1=128 from fp32 x.
//         MODE 2: A=z=gather(hW)*inv+hroot K1=64 from g_wh/g_wl planes.
// Phase1: T = relu?(A @ B1[K1,256] + bias1) -> split -> h smem planes
//         (h planes alias the dead A+B1 region).
// Phase2: out = T @ B2[256,N2] + bias2. MODE 1 -> bf16 planes (g_wh/g_wl),
//         MODE 2 -> fp32 out.
// 8 warps as 2(m) x 4(n); warp tile = 32 rows x N/4 cols. 3-product MMA.
template <int MODE>
__global__ void __launch_bounds__(256, 2)
fused_k(const float* __restrict__ x,
        const __nv_bfloat16* __restrict__ B1h, const __nv_bfloat16* __restrict__ B1l,
        const float* __restrict__ bias1,
        const __nv_bfloat16* __restrict__ B2h, const __nv_bfloat16* __restrict__ B2l,
        const float* __restrict__ bias2,
        float* __restrict__ Cf, __nv_bfloat16* __restrict__ Ch,
        __nv_bfloat16* __restrict__ Cl, int nRows) {
    constexpr int K1  = (MODE == 1) ? 128 : 64;
    constexpr int N1  = 256;
    constexpr int K2  = 256;
    constexpr int N2  = (MODE == 1) ? 128 : 64;
    constexpr bool RELU1 = true;
    constexpr bool SPLITOUT2 = (MODE == 1);
    constexpr int KC = 32;
    constexpr int NCH1 = K1 / KC, NCH2 = K2 / KC;
    constexpr int WC1 = N1 / 4, NT1 = WC1 / 8, NTG1 = WC1 / 16;
    constexpr int WC2 = N2 / 4, NT2 = WC2 / 8, NTG2 = WC2 / 16;
    constexpr int AST = K1 + 8;                    // A smem row stride (elems)
    constexpr int APL = 64 * AST * 2;              // A plane bytes
    constexpr int SB1 = N1 + 8;
    constexpr int SBB1 = KC * SB1 * 2;             // B1 chunk plane bytes
    constexpr int OB1 = 2 * APL;                   // B1 stage offset
    constexpr int HST = 264;                       // h smem row stride
    constexpr int HPL = 64 * HST * 2;              // 33792 per h plane
    constexpr int E1 = OB1 + 2 * SBB1;             // end of phase1 region
    constexpr int OB2 = (E1 > 2 * HPL) ? E1 : 2 * HPL;
    constexpr int SB2 = N2 + 8;
    constexpr int SBB2 = KC * SB2 * 2;

    extern __shared__ char dsm[];
    uint32_t sbase = smem_u32(dsm);

    const int tid = threadIdx.x;
    const int wid = tid >> 5, lane = tid & 31;
    const int wm = wid & 1, wn = wid >> 1;
    const int n0 = blockIdx.x * 64;
    int rem = nRows - n0;
    if (rem > 64) rem = 64;

    const int lrow = lane & 15, lhalf = lane >> 4;
    const int qr = lane >> 2, qc = (lane & 3) << 1;

    // ---- issue B1 chunk 0 while we gather ----
    {
        constexpr int G8 = N1 / 8;
        #pragma unroll
        for (int it = 0; it < KC * G8 / 256; it++) {
            int idx = it * 256 + tid;
            int row = idx / G8, g = idx - row * G8;
            uint32_t dst = sbase + OB1 + (uint32_t)(row * (SB1 * 2) + g * 16);
            cpa16(dst, (const char*)(B1h + (size_t)row * N1) + g * 16);
            cpa16(dst + SBB1, (const char*)(B1l + (size_t)row * N1) + g * 16);
        }
        CP_COMMIT();
    }

    // =========================== phase 0: gather ===========================
    #pragma unroll 1
    for (int r = 0; r < 8; r++) {
        int nl = wid * 8 + r;                      // local row 0..63
        int node = n0 + (nl < rem ? nl : rem - 1);
        int beg = g_rowptr[node], end = g_rowptr[node + 1];
        float s0 = 0.f, s1 = 0.f;
        if (MODE == 1) {
            for (int i = beg; i < end; i++) {
                int s = g_csr[i];
                float2 v = __ldg((const float2*)(x + (size_t)s * 64 + 2 * lane));
                s0 += v.x; s1 += v.y;
            }
        } else {
            for (int i = beg; i < end; i++) {
                int s = g_csr[i];
                size_t o = (size_t)s * 128 + 2 * lane;
                float2 h = bf2f(__ldg((const uint32_t*)(g_wh + o)));
                float2 l = bf2f(__ldg((const uint32_t*)(g_wl + o)));
                s0 += h.x + l.x; s1 += h.y + l.y;
            }
        }
        float iv = g_invdeg[node];
        uint32_t hp, lp;
        uint32_t o0 = (uint32_t)((nl * AST + 2 * lane) * 2);
        if (MODE == 1) {
            split_pair(s0 * iv, s1 * iv, hp, lp);
            *(uint32_t*)(dsm + o0) = hp;
            *(uint32_t*)(dsm + APL + o0) = lp;
            float2 xv = __ldg((const float2*)(x + (size_t)node * 64 + 2 * lane));
            split_pair(xv.x, xv.y, hp, lp);
            *(uint32_t*)(dsm + o0 + 128) = hp;          // cols 64+2*lane
            *(uint32_t*)(dsm + APL + o0 + 128) = lp;
        } else {
            size_t ro = (size_t)node * 128 + 64 + 2 * lane;
            float2 rh = bf2f(__ldg((const uint32_t*)(g_wh + ro)));
            float2 rl = bf2f(__ldg((const uint32_t*)(g_wl + ro)));
            split_pair(s0 * iv + rh.x + rl.x, s1 * iv + rh.y + rl.y, hp, lp);
            *(uint32_t*)(dsm + o0) = hp;
            *(uint32_t*)(dsm + APL + o0) = lp;
        }
    }

    // =========================== phase 1 ===========================
    {
        const int col0 = wn * WC1;
        float acc[2][NT1][4];
        #pragma unroll
        for (int mt = 0; mt < 2; mt++)
            #pragma unroll
            for (int j = 0; j < NT1; j++)
                #pragma unroll
                for (int q = 0; q < 4; q++) acc[mt][j][q] = 0.f;

        for (int c = 0; c < NCH1; c++) {
            CP_WAIT0();
            __syncthreads();   // covers gather STS (c=0) + B1 stage

            const int c0 = c * KC;
            #pragma unroll
            for (int kk = 0; kk < KC; kk += 16) {
                uint32_t ah[2][4], al[2][4];
                #pragma unroll
                for (int mt = 0; mt < 2; mt++) {
                    uint32_t ra = sbase +
                        (uint32_t)(((32 * wm + 16 * mt + lrow) * AST + c0 + kk) * 2 + lhalf * 16);
                    ldsm_x4(ah[mt], ra);
                    ldsm_x4(al[mt], ra + APL);
                }
                #pragma unroll
                for (int ng = 0; ng < NTG1; ng++) {
                    uint32_t rb = sbase + OB1 +
                        (uint32_t)(((kk + lrow) * SB1 + col0 + ng * 16) * 2 + lhalf * 16);
                    uint32_t bh[4], bl[4];
                    ldsm_x4t(bh, rb);
                    ldsm_x4t(bl, rb + SBB1);
                    #pragma unroll
                    for (int mt = 0; mt < 2; mt++) {
                        mma_bf16(acc[mt][2 * ng],     ah[mt], bh[0], bh[1]);
                        mma_bf16(acc[mt][2 * ng],     ah[mt], bl[0], bl[1]);
                        mma_bf16(acc[mt][2 * ng],     al[mt], bh[0], bh[1]);
                        mma_bf16(acc[mt][2 * ng + 1], ah[mt], bh[2], bh[3]);
                        mma_bf16(acc[mt][2 * ng + 1], ah[mt], bl[2], bl[3]);
                        mma_bf16(acc[mt][2 * ng + 1], al[mt], bh[2], bh[3]);
                    }
                }
            }
            __syncthreads();
            if (c + 1 < NCH1) {     // restage B1 for next chunk
                constexpr int G8 = N1 / 8;
                const int c0n = (c + 1) * KC;
                #pragma unroll
                for (int it = 0; it < KC * G8 / 256; it++) {
                    int idx = it * 256 + tid;
                    int row = idx / G8, g = idx - row * G8;
                    uint32_t dst = sbase + OB1 + (uint32_t)(row * (SB1 * 2) + g * 16);
                    cpa16(dst, (const char*)(B1h + (size_t)(c0n + row) * N1) + g * 16);
                    cpa16(dst + SBB1, (const char*)(B1l + (size_t)(c0n + row) * N1) + g * 16);
                }
                CP_COMMIT();
            }
        }

        // epilogue -> h smem planes (relu + split); aliases dead A/B1 region
        #pragma unroll
        for (int mt = 0; mt < 2; mt++) {
            int row0 = 32 * wm + 16 * mt + qr;
            #pragma unroll
            for (int j = 0; j < NT1; j++) {
                int col = col0 + 8 * j + qc;
                float b0 = __ldg(&bias1[col]), b1 = __ldg(&bias1[col + 1]);
                float v00 = acc[mt][j][0] + b0, v01 = acc[mt][j][1] + b1;
                float v10 = acc[mt][j][2] + b0, v11 = acc[mt][j][3] + b1;
                if (RELU1) {
                    v00 = fmaxf(v00, 0.f); v01 = fmaxf(v01, 0.f);
                    v10 = fmaxf(v10, 0.f); v11 = fmaxf(v11, 0.f);
                }
                uint32_t hp, lp;
                uint32_t o0 = (uint32_t)((row0 * HST + col) * 2);
                split_pair(v00, v01, hp, lp);
                *(uint32_t*)(dsm + o0) = hp;
                *(uint32_t*)(dsm + HPL + o0) = lp;
                uint32_t o1 = o0 + (uint32_t)(8 * HST * 2);
                split_pair(v10, v11, hp, lp);
                *(uint32_t*)(dsm + o1) = hp;
                *(uint32_t*)(dsm + HPL + o1) = lp;
            }
        }
    }
    __syncthreads();

    // =========================== phase 2 ===========================
    {
        const int col0 = wn * WC2;
        float acc[2][NT2][4];
        #pragma unroll
        for (int mt = 0; mt < 2; mt++)
            #pragma unroll
            for (int j = 0; j < NT2; j++)
                #pragma unroll
                for (int q = 0; q < 4; q++) acc[mt][j][q] = 0.f;

        for (int c = 0; c < NCH2; c++) {
            const int c0 = c * KC;
            {
                constexpr int G8 = N2 / 8;
                #pragma unroll
                for (int it = 0; it < (KC * G8 + 255) / 256; it++) {
                    int idx = it * 256 + tid;
                    if (KC * G8 % 256 == 0 || idx < KC * G8) {
                        int row = idx / G8, g = idx - row * G8;
                        uint32_t dst = sbase + OB2 + (uint32_t)(row * (SB2 * 2) + g * 16);
                        cpa16(dst, (const char*)(B2h + (size_t)(c0 + row) * N2) + g * 16);
                        cpa16(dst + SBB2, (const char*)(B2l + (size_t)(c0 + row) * N2) + g * 16);
                    }
                }
            }
            CP_COMMIT();
            CP_WAIT0();
            __syncthreads();

            #pragma unroll
            for (int kk = 0; kk < KC; kk += 16) {
                uint32_t ah[2][4], al[2][4];
                #pragma unroll
                for (int mt = 0; mt < 2; mt++) {
                    uint32_t ra = sbase +
                        (uint32_t)(((32 * wm + 16 * mt + lrow) * HST + c0 + kk) * 2 + lhalf * 16);
                    ldsm_x4(ah[mt], ra);
                    ldsm_x4(al[mt], ra + HPL);
                }
                #pragma unroll
                for (int ng = 0; ng < NTG2; ng++) {
                    uint32_t rb = sbase + OB2 +
                        (uint32_t)(((kk + lrow) * SB2 + col0 + ng * 16) * 2 + lhalf * 16);
                    uint32_t bh[4], bl[4];
                    ldsm_x4t(bh, rb);
                    ldsm_x4t(bl, rb + SBB2);
                    #pragma unroll
                    for (int mt = 0; mt < 2; mt++) {
                        mma_bf16(acc[mt][2 * ng],     ah[mt], bh[0], bh[1]);
                        mma_bf16(acc[mt][2 * ng],     ah[mt], bl[0], bl[1]);
                        mma_bf16(acc[mt][2 * ng],     al[mt], bh[0], bh[1]);
                        mma_bf16(acc[mt][2 * ng + 1], ah[mt], bh[2], bh[3]);
                        mma_bf16(acc[mt][2 * ng + 1], ah[mt], bl[2], bl[3]);
                        mma_bf16(acc[mt][2 * ng + 1], al[mt], bh[2], bh[3]);
                    }
                }
            }
            if (c + 1 < NCH2) __syncthreads();
        }

        // epilogue -> global
        #pragma unroll
        for (int mt = 0; mt < 2; mt++) {
            int row0 = 32 * wm + 16 * mt + qr;
            int row1 = row0 + 8;
            #pragma unroll
            for (int j = 0; j < NT2; j++) {
                int col = col0 + 8 * j + qc;
                float b0 = __ldg(&bias2[col]), b1 = __ldg(&bias2[col + 1]);
                float v00 = acc[mt][j][0] + b0, v01 = acc[mt][j][1] + b1;
                float v10 = acc[mt][j][2] + b0, v11 = acc[mt][j][3] + b1;
                if (SPLITOUT2) {
                    uint32_t hp, lp;
                    if (row0 < rem) {
                        size_t o = (size_t)(n0 + row0) * N2 + col;
                        split_pair(v00, v01, hp, lp);
                        *(uint32_t*)(Ch + o) = hp; *(uint32_t*)(Cl + o) = lp;
                    }
                    if (row1 < rem) {
                        size_t o = (size_t)(n0 + row1) * N2 + col;
                        split_pair(v10, v11, hp, lp);
                        *(uint32_t*)(Ch + o) = hp; *(uint32_t*)(Cl + o) = lp;
                    }
                } else {
                    if (row0 < rem)
                        *(float2*)(Cf + (size_t)(n0 + row0) * N2 + col) = make_float2(v00, v01);
                    if (row1 < rem)
                        *(float2*)(Cf + (size_t)(n0 + row1) * N2 + col) = make_float2(v10, v11);
                }
            }
        }
    }
}

// ------------------------------- launcher ----------------------------------
extern "C" void kernel_launch(void* const* d_in, const int* in_sizes, int n_in,
                              void* d_out, int out_size) {
    const float* x   = (const float*)d_in[0];
    const int*   ei  = (const int*)d_in[1];
    const float* c1W = (const float*)d_in[2];
    const float* c1r = (const float*)d_in[3];
    const float* c1b = (const float*)d_in[4];
    const float* c2W = (const float*)d_in[5];
    const float* c2r = (const float*)d_in[6];
    const float* c2b = (const float*)d_in[7];
    const float* dw1 = (const float*)d_in[8];
    const float* db1 = (const float*)d_in[9];
    const float* dw2 = (const float*)d_in[10];
    const float* db2 = (const float*)d_in[11];
    float* out = (float*)d_out;

    void *pB2c, *pWh, *pWl;
    void *pB1h, *pB1l, *pB2h, *pB2l, *pD1h, *pD1l, *pD2h, *pD2l;
    cudaGetSymbolAddress(&pB2c, g_b2c);
    cudaGetSymbolAddress(&pWh, g_wh);   cudaGetSymbolAddress(&pWl, g_wl);
    cudaGetSymbolAddress(&pB1h, g_B1h); cudaGetSymbolAddress(&pB1l, g_B1l);
    cudaGetSymbolAddress(&pB2h, g_B2h); cudaGetSymbolAddress(&pB2l, g_B2l);
    cudaGetSymbolAddress(&pD1h, g_D1h); cudaGetSymbolAddress(&pD1l, g_D1l);
    cudaGetSymbolAddress(&pD2h, g_D2h); cudaGetSymbolAddress(&pD2l, g_D2l);

    // smem sizes (see layout constants in fused_k)
    const int SM_F1 = 86016;   // MODE 1: 2*17408 + 2*16896 stage, h 67584, B2 17408
    const int SM_F2 = 76800;   // MODE 2
    cudaFuncSetAttribute(fused_k<1>, cudaFuncAttributeMaxDynamicSharedMemorySize, SM_F1);
    cudaFuncSetAttribute(fused_k<2>, cudaFuncAttributeMaxDynamicSharedMemorySize, SM_F2);

    const int nFG = (NNODES + 63) / 64;                 // 782
    const int nEdgeBlocks = (NEDGES + 255) / 256;
    const int nNodeBlocks = (NNODES + 255) / 256;

    // --- weight prep + CSR build (g_cnt zero at entry; scan3 re-zeroes) ---
    prep_k<<<128, 256>>>(c1W, c1r, c2W, c2r, c2b, dw1, dw2);
    hist_k<<<nEdgeBlocks, 256>>>(ei);
    scan1_k<<<NB_SCAN, 1024>>>();
    scan3_k<<<nNodeBlocks, 256>>>();
    place_k<<<nEdgeBlocks, 256>>>(ei);

    // --- fused gather(x) + conv1 GEMM + conv2 weight GEMM -> hWr planes ---
    fused_k<1><<<nFG, 256, SM_F1>>>(
        x, (const __nv_bfloat16*)pB1h, (const __nv_bfloat16*)pB1l, c1b,
        (const __nv_bfloat16*)pB2h, (const __nv_bfloat16*)pB2l, (const float*)pB2c,
        nullptr, (__nv_bfloat16*)pWh, (__nv_bfloat16*)pWl, NNODES);

    // --- fused gather(hWr) + decoder GEMMs -> out ---
    fused_k<2><<<nFG, 256, SM_F2>>>(
        nullptr, (const __nv_bfloat16*)pD1h, (const __nv_bfloat16*)pD1l, db1,
        (const __nv_bfloat16*)pD2h, (const __nv_bfloat16*)pD2l, db2,
        out, nullptr, nullptr, NNODES);
}

// round 8
// speedup vs baseline: 1.1830x; 1.1830x over previous
#include <cuda_runtime.h>
#include <cuda_bf16.h>
#include <math.h>
#include <stdint.h>

// ---------------------------------------------------------------------------
// GraphAE on GB300 (sm_103 plain target -> mma.sync tensor path).
// pseudo == 0 => only spline weight k=0 contributes.
// Activations carried as bf16 hi/lo plane pairs; 3-product compensated bf16
// MMA (fp32 accum) == fp32-accurate GEMMs.
// Pipeline (8 launches):
//   hist -> scanm(single-pass scan, self-zeroing cnt) -> place(zeroes flags)
//   -> agg1 -> prep -> FUSED[G1+G2] -> agg2 -> FUSED[G3+G4]
// ---------------------------------------------------------------------------

#define NNODES 50000
#define NEDGES 800000
#define NB_SCAN 49

// ------------------------- scratch (static device) -------------------------
__device__ int   g_cnt[NNODES];        // zero-init (BSS); scanm restores zero
__device__ int   g_rowptr[NNODES + 1];
__device__ int   g_cursor[NNODES];
__device__ int   g_csr[NEDGES];
__device__ float g_invdeg[NNODES];
__device__ int   g_bflag[NB_SCAN];     // scan aggregates (sentinel +1); place zeroes

// activation planes (bf16 hi/lo)
__device__ __nv_bfloat16 g_A1h[(size_t)NNODES * 128], g_A1l[(size_t)NNODES * 128];
__device__ __nv_bfloat16 g_wh[(size_t)NNODES * 128],  g_wl[(size_t)NNODES * 128]; // hWr
__device__ __nv_bfloat16 g_zh[(size_t)NNODES * 64],   g_zl[(size_t)NNODES * 64];

// bf16 hi/lo split weights, natural [k][n] row-major
__device__ __nv_bfloat16 g_B1h[128 * 256], g_B1l[128 * 256];
__device__ __nv_bfloat16 g_B2h[256 * 128], g_B2l[256 * 128];
__device__ __nv_bfloat16 g_D1h[64 * 256],  g_D1l[64 * 256];
__device__ __nv_bfloat16 g_D2h[256 * 64],  g_D2l[256 * 64];
__device__ float g_b2c[128];                   // [0 | conv2_b]

// ------------------------------ helpers ------------------------------------
__device__ __forceinline__ uint32_t smem_u32(const void* p) {
    uint32_t a;
    asm("{ .reg .u64 t; cvta.to.shared.u64 t, %1; cvt.u32.u64 %0, t; }"
        : "=r"(a) : "l"(p));
    return a;
}
__device__ __forceinline__ void ldsm_x4(uint32_t* r, uint32_t addr) {
    asm volatile("ldmatrix.sync.aligned.m8n8.x4.shared.b16 {%0,%1,%2,%3}, [%4];"
                 : "=r"(r[0]), "=r"(r[1]), "=r"(r[2]), "=r"(r[3]) : "r"(addr));
}
__device__ __forceinline__ void ldsm_x4t(uint32_t* r, uint32_t addr) {
    asm volatile("ldmatrix.sync.aligned.m8n8.x4.trans.shared.b16 {%0,%1,%2,%3}, [%4];"
                 : "=r"(r[0]), "=r"(r[1]), "=r"(r[2]), "=r"(r[3]) : "r"(addr));
}
__device__ __forceinline__ void mma_bf16(float* d, const uint32_t* a,
                                         uint32_t b0, uint32_t b1) {
    asm volatile("mma.sync.aligned.m16n8k16.row.col.f32.bf16.bf16.f32 "
                 "{%0,%1,%2,%3}, {%4,%5,%6,%7}, {%8,%9}, {%0,%1,%2,%3};"
                 : "+f"(d[0]), "+f"(d[1]), "+f"(d[2]), "+f"(d[3])
                 : "r"(a[0]), "r"(a[1]), "r"(a[2]), "r"(a[3]), "r"(b0), "r"(b1));
}
__device__ __forceinline__ void cpa16(uint32_t dst, const void* src) {
    asm volatile("cp.async.cg.shared.global [%0], [%1], 16;"
                 :: "r"(dst), "l"(src));
}
#define CP_COMMIT() asm volatile("cp.async.commit_group;" ::: "memory")
#define CP_WAIT0()  asm volatile("cp.async.wait_group 0;" ::: "memory")

__device__ __forceinline__ void split1(float v, uint16_t& h, uint16_t& l) {
    __nv_bfloat16 hb = __float2bfloat16_rn(v);
    float r = v - __bfloat162float(hb);
    __nv_bfloat16 lb = __float2bfloat16_rn(r);
    h = __bfloat16_as_ushort(hb);
    l = __bfloat16_as_ushort(lb);
}
__device__ __forceinline__ void split_pair(float a, float b, uint32_t& hp, uint32_t& lp) {
    uint16_t h0, l0, h1, l1;
    split1(a, h0, l0); split1(b, h1, l1);
    hp = (uint32_t)h0 | ((uint32_t)h1 << 16);
    lp = (uint32_t)l0 | ((uint32_t)l1 << 16);
}
__device__ __forceinline__ float2 bf2f(uint32_t u) {
    __nv_bfloat162 t = *reinterpret_cast<__nv_bfloat162*>(&u);
    return __bfloat1622float2(t);
}

// ------------------------------ weight prep --------------------------------
__global__ void prep_k(const float* __restrict__ c1W, const float* __restrict__ c1r,
                       const float* __restrict__ c2W, const float* __restrict__ c2r,
                       const float* __restrict__ c2b,
                       const float* __restrict__ dw1, const float* __restrict__ dw2) {
    int i = blockIdx.x * blockDim.x + threadIdx.x;
    uint16_t h, l;
    if (i < 128 * 256) {  // B1 [k=128][n=256]
        int k = i >> 8, n = i & 255;
        float v = (k < 64) ? c1W[k * 256 + n] : c1r[(k - 64) * 256 + n];
        split1(v, h, l);
        g_B1h[i] = __ushort_as_bfloat16(h); g_B1l[i] = __ushort_as_bfloat16(l);
    }
    if (i < 256 * 128) {  // B2 [k=256][n=128]
        int k = i >> 7, n = i & 127;
        float v = (n < 64) ? c2W[k * 64 + n] : c2r[k * 64 + (n - 64)];
        split1(v, h, l);
        g_B2h[i] = __ushort_as_bfloat16(h); g_B2l[i] = __ushort_as_bfloat16(l);
    }
    if (i < 64 * 256) {   // D1 [k=64][n=256]
        split1(dw1[i], h, l);
        g_D1h[i] = __ushort_as_bfloat16(h); g_D1l[i] = __ushort_as_bfloat16(l);
    }
    if (i < 256 * 64) {   // D2 [k=256][n=64]
        split1(dw2[i], h, l);
        g_D2h[i] = __ushort_as_bfloat16(h); g_D2l[i] = __ushort_as_bfloat16(l);
    }
    if (i < 128) g_b2c[i] = (i < 64) ? 0.0f : c2b[i - 64];
}

// ------------------------------- CSR build ---------------------------------
__global__ void hist_k(const int* __restrict__ ei) {
    int e4 = (blockIdx.x * blockDim.x + threadIdx.x) * 4;
    if (e4 < NEDGES) {
        int4 d = *(const int4*)(ei + NEDGES + e4);
        atomicAdd(&g_cnt[d.x], 1);
        atomicAdd(&g_cnt[d.y], 1);
        atomicAdd(&g_cnt[d.z], 1);
        atomicAdd(&g_cnt[d.w], 1);
    }
}

// single-pass scan: 49 blocks (all co-resident), warp-shuffle local scan,
// cross-block offsets via published aggregates (sentinel = sum+1).
// Re-zeroes g_cnt; g_bflag is zeroed by place_k after use.
__global__ void scanm_k() {
    __shared__ int wsum[32];
    __shared__ int s_boff;
    int blk = blockIdx.x, tid = threadIdx.x;
    int i = blk * 1024 + tid;
    int v = (i < NNODES) ? g_cnt[i] : 0;
    int incl = v;
    #pragma unroll
    for (int o = 1; o < 32; o <<= 1) {
        int t = __shfl_up_sync(0xffffffff, incl, o);
        if ((tid & 31) >= o) incl += t;
    }
    if ((tid & 31) == 31) wsum[tid >> 5] = incl;
    if (tid == 0) s_boff = 0;
    __syncthreads();
    if (tid < 32) {
        int w = wsum[tid];
        #pragma unroll
        for (int o = 1; o < 32; o <<= 1) {
            int t = __shfl_up_sync(0xffffffff, w, o);
            if (tid >= o) w += t;
        }
        wsum[tid] = w;                         // inclusive warp sums
    }
    __syncthreads();
    if (tid >= 32) incl += wsum[(tid >> 5) - 1];
    if (tid == 1023) atomicExch(&g_bflag[blk], wsum[31] + 1);  // publish total
    if (tid < blk) {                                           // poll predecessors
        int t;
        do { t = atomicAdd(&g_bflag[tid], 0); } while (t == 0);
        atomicAdd(&s_boff, t - 1);
    }
    __syncthreads();
    int boff = s_boff;
    if (i < NNODES) {
        int start = boff + incl - v;
        g_rowptr[i] = start;
        g_cursor[i] = start;
        g_invdeg[i] = 1.0f / fmaxf((float)v, 1.0f);
        g_cnt[i] = 0;                          // restore for next replay
        if (i == NNODES - 1) g_rowptr[NNODES] = boff + incl;
    }
}

__global__ void place_k(const int* __restrict__ ei) {
    int t = blockIdx.x * blockDim.x + threadIdx.x;
    int e4 = t * 4;
    if (e4 < NEDGES) {
        int4 d = *(const int4*)(ei + NEDGES + e4);
        int4 s = *(const int4*)(ei + e4);
        g_csr[atomicAdd(&g_cursor[d.x], 1)] = s.x;
        g_csr[atomicAdd(&g_cursor[d.y], 1)] = s.y;
        g_csr[atomicAdd(&g_cursor[d.z], 1)] = s.z;
        g_csr[atomicAdd(&g_cursor[d.w], 1)] = s.w;
    }
    if (t < NB_SCAN) g_bflag[t] = 0;           // reset scan flags for next replay
}

// --------------------------- gather aggregations ---------------------------
// warp per node; lane owns feature pair (2*lane, 2*lane+1)
__global__ void agg1_k(const float* __restrict__ x) {
    int gt = blockIdx.x * blockDim.x + threadIdx.x;
    int node = gt >> 5;
    if (node >= NNODES) return;
    int lane = gt & 31;
    int beg = g_rowptr[node], end = g_rowptr[node + 1];
    float s0 = 0.f, s1 = 0.f;
    for (int i = beg; i < end; i++) {
        int s = g_csr[i];
        float2 v = __ldg((const float2*)(x + (size_t)s * 64 + 2 * lane));
        s0 += v.x; s1 += v.y;
    }
    float iv = g_invdeg[node];
    float2 xv = __ldg((const float2*)(x + (size_t)node * 64 + 2 * lane));
    uint32_t hp, lp;
    size_t o = (size_t)node * 128 + 2 * lane;
    split_pair(s0 * iv, s1 * iv, hp, lp);
    *(uint32_t*)(g_A1h + o) = hp; *(uint32_t*)(g_A1l + o) = lp;
    split_pair(xv.x, xv.y, hp, lp);
    *(uint32_t*)(g_A1h + o + 64) = hp; *(uint32_t*)(g_A1l + o + 64) = lp;
}

// z = gather(hW)*invdeg + hroot (hW = cols 0:64 of hWr planes, hroot 64:128)
__global__ void agg2_k() {
    int gt = blockIdx.x * blockDim.x + threadIdx.x;
    int node = gt >> 5;
    if (node >= NNODES) return;
    int lane = gt & 31;
    int beg = g_rowptr[node], end = g_rowptr[node + 1];
    float s0 = 0.f, s1 = 0.f;
    for (int i = beg; i < end; i++) {
        int s = g_csr[i];
        size_t o = (size_t)s * 128 + 2 * lane;
        float2 h = bf2f(__ldg((const uint32_t*)(g_wh + o)));
        float2 l = bf2f(__ldg((const uint32_t*)(g_wl + o)));
        s0 += h.x + l.x; s1 += h.y + l.y;
    }
    float iv = g_invdeg[node];
    size_t ro = (size_t)node * 128 + 64 + 2 * lane;
    float2 rh = bf2f(*(const uint32_t*)(g_wh + ro));
    float2 rl = bf2f(*(const uint32_t*)(g_wl + ro));
    float z0 = s0 * iv + rh.x + rl.x;
    float z1 = s1 * iv + rh.y + rl.y;
    uint32_t hp, lp;
    split_pair(z0, z1, hp, lp);
    size_t zo = (size_t)node * 64 + 2 * lane;
    *(uint32_t*)(g_zh + zo) = hp; *(uint32_t*)(g_zl + zo) = lp;
}

// -------------------- fused two-GEMM kernel (64-row tile) ------------------
// Phase1: T = relu(A[64,K1] @ B1[K1,N1=256] + bias1) -> split -> smem planes
// Phase2: out = T @ B2[K2=N1,N2] + bias2 (SPLITOUT2: bf16 planes, else fp32)
// 8 warps as 2(m) x 4(n); warp tile = 32 rows x N/4 cols. 3-product MMA.
template <int K1, int N1, int K2, int N2, bool SPLITOUT2>
__global__ void __launch_bounds__(256, 2)
fused2_k(const __nv_bfloat16* __restrict__ Ah, const __nv_bfloat16* __restrict__ Al,
         const __nv_bfloat16* __restrict__ B1h, const __nv_bfloat16* __restrict__ B1l,
         const float* __restrict__ bias1,
         const __nv_bfloat16* __restrict__ B2h, const __nv_bfloat16* __restrict__ B2l,
         const float* __restrict__ bias2,
         float* __restrict__ Cf, __nv_bfloat16* __restrict__ Ch,
         __nv_bfloat16* __restrict__ Cl, int nRows) {
    static_assert(N1 == 256 && K2 == N1, "layout assumes N1=256");
    constexpr int KC = 32;
    constexpr int NCH1 = K1 / KC, NCH2 = K2 / KC;
    constexpr int WC1 = N1 / 4, NT1 = WC1 / 8, NTG1 = WC1 / 16;
    constexpr int WC2 = N2 / 4, NT2 = WC2 / 8, NTG2 = WC2 / 16;
    constexpr int SB1 = N1 + 8, SB2 = N2 + 8;
    constexpr int HST = 264;                       // h smem row stride (elems)
    constexpr int HPL = 64 * HST * 2;              // 33792 bytes per h plane
    constexpr int OA  = 2 * HPL;                   // 67584: A stage
    constexpr int APL = 64 * 40 * 2;               // 5120 per A plane
    constexpr int OBB = OA + 2 * APL;              // 77824: B stage
    constexpr int SBB1 = KC * SB1 * 2;             // B plane bytes phase1
    constexpr int SBB2 = KC * SB2 * 2;             // phase2

    extern __shared__ char dsm[];
    uint32_t sbase = smem_u32(dsm);

    const int tid = threadIdx.x;
    const int wid = tid >> 5, lane = tid & 31;
    const int wm = wid & 1, wn = wid >> 1;
    const int n0 = blockIdx.x * 64;
    int rem = nRows - n0;
    if (rem > 64) rem = 64;

    const int lrow = lane & 15, lhalf = lane >> 4;
    const int qr = lane >> 2, qc = (lane & 3) << 1;

    // =========================== phase 1 ===========================
    {
        const int col0 = wn * WC1;
        float acc[2][NT1][4];
        #pragma unroll
        for (int mt = 0; mt < 2; mt++)
            #pragma unroll
            for (int j = 0; j < NT1; j++)
                #pragma unroll
                for (int q = 0; q < 4; q++) acc[mt][j][q] = 0.f;

        for (int c = 0; c < NCH1; c++) {
            const int c0 = c * KC;
            // stage A chunk: 64 rows x 32 cols, both planes (256 x 16B each)
            {
                int row = tid >> 2, j = tid & 3;
                int gr = n0 + (row < rem ? row : rem - 1);
                uint32_t dst = sbase + OA + (uint32_t)(row * 80 + j * 16);
                cpa16(dst, (const char*)(Ah + (size_t)gr * K1 + c0) + j * 16);
                cpa16(dst + APL, (const char*)(Al + (size_t)gr * K1 + c0) + j * 16);
            }
            // stage B1 chunk: 32 rows x N1, both planes
            {
                constexpr int G8 = N1 / 8;
                #pragma unroll
                for (int it = 0; it < KC * G8 / 256; it++) {
                    int idx = it * 256 + tid;
                    int row = idx / G8, g = idx - row * G8;
                    uint32_t dst = sbase + OBB + (uint32_t)(row * (SB1 * 2) + g * 16);
                    cpa16(dst, (const char*)(B1h + (size_t)(c0 + row) * N1) + g * 16);
                    cpa16(dst + SBB1, (const char*)(B1l + (size_t)(c0 + row) * N1) + g * 16);
                }
            }
            CP_COMMIT();
            CP_WAIT0();
            __syncthreads();

            #pragma unroll
            for (int kk = 0; kk < KC; kk += 16) {
                uint32_t ah[2][4], al[2][4];
                #pragma unroll
                for (int mt = 0; mt < 2; mt++) {
                    uint32_t ra = sbase + OA +
                        (uint32_t)((32 * wm + 16 * mt + lrow) * 80 + kk * 2 + lhalf * 16);
                    ldsm_x4(ah[mt], ra);
                    ldsm_x4(al[mt], ra + APL);
                }
                #pragma unroll
                for (int ng = 0; ng < NTG1; ng++) {
                    uint32_t rb = sbase + OBB +
                        (uint32_t)(((kk + lrow) * SB1 + col0 + ng * 16) * 2 + lhalf * 16);
                    uint32_t bh[4], bl[4];
                    ldsm_x4t(bh, rb);
                    ldsm_x4t(bl, rb + SBB1);
                    #pragma unroll
                    for (int mt = 0; mt < 2; mt++) {
                        mma_bf16(acc[mt][2 * ng],     ah[mt], bh[0], bh[1]);
                        mma_bf16(acc[mt][2 * ng],     ah[mt], bl[0], bl[1]);
                        mma_bf16(acc[mt][2 * ng],     al[mt], bh[0], bh[1]);
                        mma_bf16(acc[mt][2 * ng + 1], ah[mt], bh[2], bh[3]);
                        mma_bf16(acc[mt][2 * ng + 1], ah[mt], bl[2], bl[3]);
                        mma_bf16(acc[mt][2 * ng + 1], al[mt], bh[2], bh[3]);
                    }
                }
            }
            __syncthreads();   // before next chunk restages (or phase2 stages)
        }

        // epilogue -> h smem planes (relu + split)
        #pragma unroll
        for (int mt = 0; mt < 2; mt++) {
            int row0 = 32 * wm + 16 * mt + qr;
            #pragma unroll
            for (int j = 0; j < NT1; j++) {
                int col = col0 + 8 * j + qc;
                float b0 = __ldg(&bias1[col]), b1 = __ldg(&bias1[col + 1]);
                float v00 = fmaxf(acc[mt][j][0] + b0, 0.f);
                float v01 = fmaxf(acc[mt][j][1] + b1, 0.f);
                float v10 = fmaxf(acc[mt][j][2] + b0, 0.f);
                float v11 = fmaxf(acc[mt][j][3] + b1, 0.f);
                uint32_t hp, lp;
                uint32_t o0 = (uint32_t)((row0 * HST + col) * 2);
                split_pair(v00, v01, hp, lp);
                *(uint32_t*)(dsm + o0) = hp;
                *(uint32_t*)(dsm + HPL + o0) = lp;
                uint32_t o1 = o0 + (uint32_t)(8 * HST * 2);
                split_pair(v10, v11, hp, lp);
                *(uint32_t*)(dsm + o1) = hp;
                *(uint32_t*)(dsm + HPL + o1) = lp;
            }
        }
    }
    __syncthreads();

    // =========================== phase 2 ===========================
    {
        const int col0 = wn * WC2;
        float acc[2][NT2][4];
        #pragma unroll
        for (int mt = 0; mt < 2; mt++)
            #pragma unroll
            for (int j = 0; j < NT2; j++)
                #pragma unroll
                for (int q = 0; q < 4; q++) acc[mt][j][q] = 0.f;

        for (int c = 0; c < NCH2; c++) {
            const int c0 = c * KC;
            // stage B2 chunk
            {
                constexpr int G8 = N2 / 8;
                #pragma unroll
                for (int it = 0; it < (KC * G8 + 255) / 256; it++) {
                    int idx = it * 256 + tid;
                    if (KC * G8 % 256 == 0 || idx < KC * G8) {
                        int row = idx / G8, g = idx - row * G8;
                        uint32_t dst = sbase + OBB + (uint32_t)(row * (SB2 * 2) + g * 16);
                        cpa16(dst, (const char*)(B2h + (size_t)(c0 + row) * N2) + g * 16);
                        cpa16(dst + SBB2, (const char*)(B2l + (size_t)(c0 + row) * N2) + g * 16);
                    }
                }
            }
            CP_COMMIT();
            CP_WAIT0();
            __syncthreads();

            #pragma unroll
            for (int kk = 0; kk < KC; kk += 16) {
                uint32_t ah[2][4], al[2][4];
                #pragma unroll
                for (int mt = 0; mt < 2; mt++) {
                    uint32_t ra = sbase +
                        (uint32_t)(((32 * wm + 16 * mt + lrow) * HST + c0 + kk) * 2 + lhalf * 16);
                    ldsm_x4(ah[mt], ra);
                    ldsm_x4(al[mt], ra + HPL);
                }
                #pragma unroll
                for (int ng = 0; ng < NTG2; ng++) {
                    uint32_t rb = sbase + OBB +
                        (uint32_t)(((kk + lrow) * SB2 + col0 + ng * 16) * 2 + lhalf * 16);
                    uint32_t bh[4], bl[4];
                    ldsm_x4t(bh, rb);
                    ldsm_x4t(bl, rb + SBB2);
                    #pragma unroll
                    for (int mt = 0; mt < 2; mt++) {
                        mma_bf16(acc[mt][2 * ng],     ah[mt], bh[0], bh[1]);
                        mma_bf16(acc[mt][2 * ng],     ah[mt], bl[0], bl[1]);
                        mma_bf16(acc[mt][2 * ng],     al[mt], bh[0], bh[1]);
                        mma_bf16(acc[mt][2 * ng + 1], ah[mt], bh[2], bh[3]);
                        mma_bf16(acc[mt][2 * ng + 1], ah[mt], bl[2], bl[3]);
                        mma_bf16(acc[mt][2 * ng + 1], al[mt], bh[2], bh[3]);
                    }
                }
            }
            if (c + 1 < NCH2) __syncthreads();
        }

        // epilogue -> global
        #pragma unroll
        for (int mt = 0; mt < 2; mt++) {
            int row0 = 32 * wm + 16 * mt + qr;
            int row1 = row0 + 8;
            #pragma unroll
            for (int j = 0; j < NT2; j++) {
                int col = col0 + 8 * j + qc;
                float b0 = __ldg(&bias2[col]), b1 = __ldg(&bias2[col + 1]);
                float v00 = acc[mt][j][0] + b0, v01 = acc[mt][j][1] + b1;
                float v10 = acc[mt][j][2] + b0, v11 = acc[mt][j][3] + b1;
                if (SPLITOUT2) {
                    uint32_t hp, lp;
                    if (row0 < rem) {
                        size_t o = (size_t)(n0 + row0) * N2 + col;
                        split_pair(v00, v01, hp, lp);
                        *(uint32_t*)(Ch + o) = hp; *(uint32_t*)(Cl + o) = lp;
                    }
                    if (row1 < rem) {
                        size_t o = (size_t)(n0 + row1) * N2 + col;
                        split_pair(v10, v11, hp, lp);
                        *(uint32_t*)(Ch + o) = hp; *(uint32_t*)(Cl + o) = lp;
                    }
                } else {
                    if (row0 < rem)
                        *(float2*)(Cf + (size_t)(n0 + row0) * N2 + col) = make_float2(v00, v01);
                    if (row1 < rem)
                        *(float2*)(Cf + (size_t)(n0 + row1) * N2 + col) = make_float2(v10, v11);
                }
            }
        }
    }
}

// ------------------------------- launcher ----------------------------------
extern "C" void kernel_launch(void* const* d_in, const int* in_sizes, int n_in,
                              void* d_out, int out_size) {
    const float* x   = (const float*)d_in[0];
    const int*   ei  = (const int*)d_in[1];
    const float* c1W = (const float*)d_in[2];
    const float* c1r = (const float*)d_in[3];
    const float* c1b = (const float*)d_in[4];
    const float* c2W = (const float*)d_in[5];
    const float* c2r = (const float*)d_in[6];
    const float* c2b = (const float*)d_in[7];
    const float* dw1 = (const float*)d_in[8];
    const float* db1 = (const float*)d_in[9];
    const float* dw2 = (const float*)d_in[10];
    const float* db2 = (const float*)d_in[11];
    float* out = (float*)d_out;

    void *pB2c;
    void *pA1h, *pA1l, *pWh, *pWl, *pZh, *pZl;
    void *pB1h, *pB1l, *pB2h, *pB2l, *pD1h, *pD1l, *pD2h, *pD2l;
    cudaGetSymbolAddress(&pB2c, g_b2c);
    cudaGetSymbolAddress(&pA1h, g_A1h); cudaGetSymbolAddress(&pA1l, g_A1l);
    cudaGetSymbolAddress(&pWh, g_wh);   cudaGetSymbolAddress(&pWl, g_wl);
    cudaGetSymbolAddress(&pZh, g_zh);   cudaGetSymbolAddress(&pZl, g_zl);
    cudaGetSymbolAddress(&pB1h, g_B1h); cudaGetSymbolAddress(&pB1l, g_B1l);
    cudaGetSymbolAddress(&pB2h, g_B2h); cudaGetSymbolAddress(&pB2l, g_B2l);
    cudaGetSymbolAddress(&pD1h, g_D1h); cudaGetSymbolAddress(&pD1l, g_D1l);
    cudaGetSymbolAddress(&pD2h, g_D2h); cudaGetSymbolAddress(&pD2l, g_D2l);

    // smem: h planes 67584 + A stage 10240 + B stage 2*KC*(N1+8)*2 = 33792
    const int SM_F = 67584 + 10240 + 33792;  // 111616 -> occ 2
    cudaFuncSetAttribute(fused2_k<128, 256, 256, 128, true>,
                         cudaFuncAttributeMaxDynamicSharedMemorySize, SM_F);
    cudaFuncSetAttribute(fused2_k<64, 256, 256, 64, false>,
                         cudaFuncAttributeMaxDynamicSharedMemorySize, SM_F);

    const int nFG = (NNODES + 63) / 64;                 // 782
    const int nE4Blocks = (NEDGES / 4 + 255) / 256;     // 782
    const int nAggBlocks = (NNODES * 32 + 255) / 256;   // 6250

    // --- CSR build (g_cnt zero at entry; scanm re-zeroes; place zeroes flags)
    hist_k<<<nE4Blocks, 256>>>(ei);
    scanm_k<<<NB_SCAN, 1024>>>();
    place_k<<<nE4Blocks, 256>>>(ei);

    // --- conv1 input aggregation (ncu capture slot #4) ---
    agg1_k<<<nAggBlocks, 256>>>(x);
    prep_k<<<128, 256>>>(c1W, c1r, c2W, c2r, c2b, dw1, dw2);

    // --- fused conv1 GEMM + conv2 weight GEMM: A1 -> h(smem) -> hWr ---
    fused2_k<128, 256, 256, 128, true><<<nFG, 256, SM_F>>>(
        (const __nv_bfloat16*)pA1h, (const __nv_bfloat16*)pA1l,
        (const __nv_bfloat16*)pB1h, (const __nv_bfloat16*)pB1l, c1b,
        (const __nv_bfloat16*)pB2h, (const __nv_bfloat16*)pB2l, (const float*)pB2c,
        nullptr, (__nv_bfloat16*)pWh, (__nv_bfloat16*)pWl, NNODES);

    // --- conv2 aggregation -> z ---
    agg2_k<<<nAggBlocks, 256>>>();

    // --- fused decoder: z -> h2(smem) -> out ---
    fused2_k<64, 256, 256, 64, false><<<nFG, 256, SM_F>>>(
        (const __nv_bfloat16*)pZh, (const __nv_bfloat16*)pZl,
        (const __nv_bfloat16*)pD1h, (const __nv_bfloat16*)pD1l, db1,
        (const __nv_bfloat16*)pD2h, (const __nv_bfloat16*)pD2l, db2,
        out, nullptr, nullptr, NNODES);
}

// round 9
// speedup vs baseline: 1.2072x; 1.0205x over previous
#include <cuda_runtime.h>
#include <cuda_bf16.h>
#include <math.h>
#include <stdint.h>

// ---------------------------------------------------------------------------
// GraphAE on GB300 (sm_103 plain target -> mma.sync tensor path).
// pseudo == 0 => only spline weight k=0 contributes.
// Activations as bf16 hi/lo plane pairs; 3-product compensated bf16 MMA
// (fp32 accum) == fp32-accurate GEMMs.
// Pipeline (8 launches):
//   hist -> scanm -> place -> agg1 -> prep -> FUSED[G1+G2] -> agg2
//   -> FUSED[G3+G4]
// Fused kernels double-buffer their cp.async stages by aliasing the dead
// h-plane region (phase1) / dead stage region (phase2) — no extra smem.
// ---------------------------------------------------------------------------

#define NNODES 50000
#define NEDGES 800000
#define NB_SCAN 49

// ------------------------- scratch (static device) -------------------------
__device__ int   g_cnt[NNODES];        // zero-init (BSS); scanm restores zero
__device__ int   g_rowptr[NNODES + 1];
__device__ int   g_cursor[NNODES];
__device__ int   g_csr[NEDGES];
__device__ float g_invdeg[NNODES];
__device__ int   g_bflag[NB_SCAN];     // scan aggregates (sentinel +1); place zeroes

// activation planes (bf16 hi/lo)
__device__ __nv_bfloat16 g_A1h[(size_t)NNODES * 128], g_A1l[(size_t)NNODES * 128];
__device__ __nv_bfloat16 g_wh[(size_t)NNODES * 128],  g_wl[(size_t)NNODES * 128]; // hWr
__device__ __nv_bfloat16 g_zh[(size_t)NNODES * 64],   g_zl[(size_t)NNODES * 64];

// bf16 hi/lo split weights, natural [k][n] row-major
__device__ __nv_bfloat16 g_B1h[128 * 256], g_B1l[128 * 256];
__device__ __nv_bfloat16 g_B2h[256 * 128], g_B2l[256 * 128];
__device__ __nv_bfloat16 g_D1h[64 * 256],  g_D1l[64 * 256];
__device__ __nv_bfloat16 g_D2h[256 * 64],  g_D2l[256 * 64];
__device__ float g_b2c[128];                   // [0 | conv2_b]

// ------------------------------ helpers ------------------------------------
__device__ __forceinline__ uint32_t smem_u32(const void* p) {
    uint32_t a;
    asm("{ .reg .u64 t; cvta.to.shared.u64 t, %1; cvt.u32.u64 %0, t; }"
        : "=r"(a) : "l"(p));
    return a;
}
__device__ __forceinline__ void ldsm_x4(uint32_t* r, uint32_t addr) {
    asm volatile("ldmatrix.sync.aligned.m8n8.x4.shared.b16 {%0,%1,%2,%3}, [%4];"
                 : "=r"(r[0]), "=r"(r[1]), "=r"(r[2]), "=r"(r[3]) : "r"(addr));
}
__device__ __forceinline__ void ldsm_x4t(uint32_t* r, uint32_t addr) {
    asm volatile("ldmatrix.sync.aligned.m8n8.x4.trans.shared.b16 {%0,%1,%2,%3}, [%4];"
                 : "=r"(r[0]), "=r"(r[1]), "=r"(r[2]), "=r"(r[3]) : "r"(addr));
}
__device__ __forceinline__ void mma_bf16(float* d, const uint32_t* a,
                                         uint32_t b0, uint32_t b1) {
    asm volatile("mma.sync.aligned.m16n8k16.row.col.f32.bf16.bf16.f32 "
                 "{%0,%1,%2,%3}, {%4,%5,%6,%7}, {%8,%9}, {%0,%1,%2,%3};"
                 : "+f"(d[0]), "+f"(d[1]), "+f"(d[2]), "+f"(d[3])
                 : "r"(a[0]), "r"(a[1]), "r"(a[2]), "r"(a[3]), "r"(b0), "r"(b1));
}
__device__ __forceinline__ void cpa16(uint32_t dst, const void* src) {
    asm volatile("cp.async.cg.shared.global [%0], [%1], 16;"
                 :: "r"(dst), "l"(src));
}
#define CP_COMMIT() asm volatile("cp.async.commit_group;" ::: "memory")
#define CP_WAIT0()  asm volatile("cp.async.wait_group 0;" ::: "memory")
#define CP_WAIT1()  asm volatile("cp.async.wait_group 1;" ::: "memory")

__device__ __forceinline__ void split1(float v, uint16_t& h, uint16_t& l) {
    __nv_bfloat16 hb = __float2bfloat16_rn(v);
    float r = v - __bfloat162float(hb);
    __nv_bfloat16 lb = __float2bfloat16_rn(r);
    h = __bfloat16_as_ushort(hb);
    l = __bfloat16_as_ushort(lb);
}
__device__ __forceinline__ void split_pair(float a, float b, uint32_t& hp, uint32_t& lp) {
    uint16_t h0, l0, h1, l1;
    split1(a, h0, l0); split1(b, h1, l1);
    hp = (uint32_t)h0 | ((uint32_t)h1 << 16);
    lp = (uint32_t)l0 | ((uint32_t)l1 << 16);
}
__device__ __forceinline__ float2 bf2f(uint32_t u) {
    __nv_bfloat162 t = *reinterpret_cast<__nv_bfloat162*>(&u);
    return __bfloat1622float2(t);
}

// ------------------------------ weight prep --------------------------------
__global__ void prep_k(const float* __restrict__ c1W, const float* __restrict__ c1r,
                       const float* __restrict__ c2W, const float* __restrict__ c2r,
                       const float* __restrict__ c2b,
                       const float* __restrict__ dw1, const float* __restrict__ dw2) {
    int i = blockIdx.x * blockDim.x + threadIdx.x;
    uint16_t h, l;
    if (i < 128 * 256) {  // B1 [k=128][n=256]
        int k = i >> 8, n = i & 255;
        float v = (k < 64) ? c1W[k * 256 + n] : c1r[(k - 64) * 256 + n];
        split1(v, h, l);
        g_B1h[i] = __ushort_as_bfloat16(h); g_B1l[i] = __ushort_as_bfloat16(l);
    }
    if (i < 256 * 128) {  // B2 [k=256][n=128]
        int k = i >> 7, n = i & 127;
        float v = (n < 64) ? c2W[k * 64 + n] : c2r[k * 64 + (n - 64)];
        split1(v, h, l);
        g_B2h[i] = __ushort_as_bfloat16(h); g_B2l[i] = __ushort_as_bfloat16(l);
    }
    if (i < 64 * 256) {   // D1 [k=64][n=256]
        split1(dw1[i], h, l);
        g_D1h[i] = __ushort_as_bfloat16(h); g_D1l[i] = __ushort_as_bfloat16(l);
    }
    if (i < 256 * 64) {   // D2 [k=256][n=64]
        split1(dw2[i], h, l);
        g_D2h[i] = __ushort_as_bfloat16(h); g_D2l[i] = __ushort_as_bfloat16(l);
    }
    if (i < 128) g_b2c[i] = (i < 64) ? 0.0f : c2b[i - 64];
}

// ------------------------------- CSR build ---------------------------------
__global__ void hist_k(const int* __restrict__ ei) {
    int e4 = (blockIdx.x * blockDim.x + threadIdx.x) * 4;
    if (e4 < NEDGES) {
        int4 d = *(const int4*)(ei + NEDGES + e4);
        atomicAdd(&g_cnt[d.x], 1);
        atomicAdd(&g_cnt[d.y], 1);
        atomicAdd(&g_cnt[d.z], 1);
        atomicAdd(&g_cnt[d.w], 1);
    }
}

// single-pass scan: 49 co-resident blocks, warp-shuffle local scan,
// cross-block offsets via published aggregates (sentinel = sum+1).
// Re-zeroes g_cnt; g_bflag is zeroed by place_k after use.
__global__ void scanm_k() {
    __shared__ int wsum[32];
    __shared__ int s_boff;
    int blk = blockIdx.x, tid = threadIdx.x;
    int i = blk * 1024 + tid;
    int v = (i < NNODES) ? g_cnt[i] : 0;
    int incl = v;
    #pragma unroll
    for (int o = 1; o < 32; o <<= 1) {
        int t = __shfl_up_sync(0xffffffff, incl, o);
        if ((tid & 31) >= o) incl += t;
    }
    if ((tid & 31) == 31) wsum[tid >> 5] = incl;
    if (tid == 0) s_boff = 0;
    __syncthreads();
    if (tid < 32) {
        int w = wsum[tid];
        #pragma unroll
        for (int o = 1; o < 32; o <<= 1) {
            int t = __shfl_up_sync(0xffffffff, w, o);
            if (tid >= o) w += t;
        }
        wsum[tid] = w;                         // inclusive warp sums
    }
    __syncthreads();
    if (tid >= 32) incl += wsum[(tid >> 5) - 1];
    if (tid == 1023) atomicExch(&g_bflag[blk], wsum[31] + 1);  // publish total
    if (tid < blk) {                                           // poll predecessors
        int t;
        do { t = atomicAdd(&g_bflag[tid], 0); } while (t == 0);
        atomicAdd(&s_boff, t - 1);
    }
    __syncthreads();
    int boff = s_boff;
    if (i < NNODES) {
        int start = boff + incl - v;
        g_rowptr[i] = start;
        g_cursor[i] = start;
        g_invdeg[i] = 1.0f / fmaxf((float)v, 1.0f);
        g_cnt[i] = 0;                          // restore for next replay
        if (i == NNODES - 1) g_rowptr[NNODES] = boff + incl;
    }
}

__global__ void place_k(const int* __restrict__ ei) {
    int t = blockIdx.x * blockDim.x + threadIdx.x;
    int e4 = t * 4;
    if (e4 < NEDGES) {
        int4 d = *(const int4*)(ei + NEDGES + e4);
        int4 s = *(const int4*)(ei + e4);
        g_csr[atomicAdd(&g_cursor[d.x], 1)] = s.x;
        g_csr[atomicAdd(&g_cursor[d.y], 1)] = s.y;
        g_csr[atomicAdd(&g_cursor[d.z], 1)] = s.z;
        g_csr[atomicAdd(&g_cursor[d.w], 1)] = s.w;
    }
    if (t < NB_SCAN) g_bflag[t] = 0;           // reset scan flags for next replay
}

// --------------------------- gather aggregations ---------------------------
// warp per node; lane owns feature pair (2*lane, 2*lane+1); 4-way MLP unroll.
__global__ void agg1_k(const float* __restrict__ x) {
    int gt = blockIdx.x * blockDim.x + threadIdx.x;
    int node = gt >> 5;
    if (node >= NNODES) return;
    int lane = gt & 31;
    int beg = g_rowptr[node], end = g_rowptr[node + 1];
    float s0 = 0.f, s1 = 0.f;
    int i = beg;
    for (; i + 4 <= end; i += 4) {
        int sa = g_csr[i], sb = g_csr[i + 1], sc = g_csr[i + 2], sd = g_csr[i + 3];
        float2 va = __ldg((const float2*)(x + (size_t)sa * 64 + 2 * lane));
        float2 vb = __ldg((const float2*)(x + (size_t)sb * 64 + 2 * lane));
        float2 vc = __ldg((const float2*)(x + (size_t)sc * 64 + 2 * lane));
        float2 vd = __ldg((const float2*)(x + (size_t)sd * 64 + 2 * lane));
        s0 += (va.x + vb.x) + (vc.x + vd.x);
        s1 += (va.y + vb.y) + (vc.y + vd.y);
    }
    for (; i < end; i++) {
        int s = g_csr[i];
        float2 v = __ldg((const float2*)(x + (size_t)s * 64 + 2 * lane));
        s0 += v.x; s1 += v.y;
    }
    float iv = g_invdeg[node];
    float2 xv = __ldg((const float2*)(x + (size_t)node * 64 + 2 * lane));
    uint32_t hp, lp;
    size_t o = (size_t)node * 128 + 2 * lane;
    split_pair(s0 * iv, s1 * iv, hp, lp);
    *(uint32_t*)(g_A1h + o) = hp; *(uint32_t*)(g_A1l + o) = lp;
    split_pair(xv.x, xv.y, hp, lp);
    *(uint32_t*)(g_A1h + o + 64) = hp; *(uint32_t*)(g_A1l + o + 64) = lp;
}

// z = gather(hW)*invdeg + hroot (hW = cols 0:64 of hWr planes, hroot 64:128)
__global__ void agg2_k() {
    int gt = blockIdx.x * blockDim.x + threadIdx.x;
    int node = gt >> 5;
    if (node >= NNODES) return;
    int lane = gt & 31;
    int beg = g_rowptr[node], end = g_rowptr[node + 1];
    float s0 = 0.f, s1 = 0.f;
    int i = beg;
    for (; i + 4 <= end; i += 4) {
        int sa = g_csr[i], sb = g_csr[i + 1], sc = g_csr[i + 2], sd = g_csr[i + 3];
        size_t oa = (size_t)sa * 128 + 2 * lane, ob = (size_t)sb * 128 + 2 * lane;
        size_t oc = (size_t)sc * 128 + 2 * lane, od = (size_t)sd * 128 + 2 * lane;
        float2 ha = bf2f(__ldg((const uint32_t*)(g_wh + oa)));
        float2 hb = bf2f(__ldg((const uint32_t*)(g_wh + ob)));
        float2 hc = bf2f(__ldg((const uint32_t*)(g_wh + oc)));
        float2 hd = bf2f(__ldg((const uint32_t*)(g_wh + od)));
        float2 la = bf2f(__ldg((const uint32_t*)(g_wl + oa)));
        float2 lb = bf2f(__ldg((const uint32_t*)(g_wl + ob)));
        float2 lc = bf2f(__ldg((const uint32_t*)(g_wl + oc)));
        float2 ld = bf2f(__ldg((const uint32_t*)(g_wl + od)));
        s0 += ((ha.x + la.x) + (hb.x + lb.x)) + ((hc.x + lc.x) + (hd.x + ld.x));
        s1 += ((ha.y + la.y) + (hb.y + lb.y)) + ((hc.y + lc.y) + (hd.y + ld.y));
    }
    for (; i < end; i++) {
        int s = g_csr[i];
        size_t o = (size_t)s * 128 + 2 * lane;
        float2 h = bf2f(__ldg((const uint32_t*)(g_wh + o)));
        float2 l = bf2f(__ldg((const uint32_t*)(g_wl + o)));
        s0 += h.x + l.x; s1 += h.y + l.y;
    }
    float iv = g_invdeg[node];
    size_t ro = (size_t)node * 128 + 64 + 2 * lane;
    float2 rh = bf2f(*(const uint32_t*)(g_wh + ro));
    float2 rl = bf2f(*(const uint32_t*)(g_wl + ro));
    float z0 = s0 * iv + rh.x + rl.x;
    float z1 = s1 * iv + rh.y + rl.y;
    uint32_t hp, lp;
    split_pair(z0, z1, hp, lp);
    size_t zo = (size_t)node * 64 + 2 * lane;
    *(uint32_t*)(g_zh + zo) = hp; *(uint32_t*)(g_zl + zo) = lp;
}

// -------------------- fused two-GEMM kernel (64-row tile) ------------------
// Phase1: T = relu(A[64,K1] @ B1[K1,N1=256] + bias1) -> split -> h smem
// Phase2: out = T @ B2[K2=N1,N2] + bias2 (SPLITOUT2: bf16 planes, else fp32)
// Double-buffered stages: phase1 buf1 aliases the (then-dead) h region; the
// last phase1 chunk is odd -> lives in buf1, dead exactly when the epilogue
// overwrites it. Phase2 double-buffers B2 in the dead phase1 stage region.
// 8 warps as 2(m) x 4(n); warp tile = 32 rows x N/4 cols. 3-product MMA.
template <int K1, int N1, int K2, int N2, bool SPLITOUT2>
__global__ void __launch_bounds__(256, 2)
fused2_k(const __nv_bfloat16* __restrict__ Ah, const __nv_bfloat16* __restrict__ Al,
         const __nv_bfloat16* __restrict__ B1h, const __nv_bfloat16* __restrict__ B1l,
         const float* __restrict__ bias1,
         const __nv_bfloat16* __restrict__ B2h, const __nv_bfloat16* __restrict__ B2l,
         const float* __restrict__ bias2,
         float* __restrict__ Cf, __nv_bfloat16* __restrict__ Ch,
         __nv_bfloat16* __restrict__ Cl, int nRows) {
    static_assert(N1 == 256 && K2 == N1, "layout assumes N1=256");
    constexpr int KC = 32;
    constexpr int NCH1 = K1 / KC, NCH2 = K2 / KC;
    static_assert(NCH1 % 2 == 0, "last phase1 chunk must land in buf1");
    constexpr int WC1 = N1 / 4, NT1 = WC1 / 8, NTG1 = WC1 / 16;
    constexpr int WC2 = N2 / 4, NT2 = WC2 / 8, NTG2 = WC2 / 16;
    constexpr int SB1 = N1 + 8, SB2 = N2 + 8;
    constexpr int HST = 264;                       // h smem row stride (elems)
    constexpr int HPL = 64 * HST * 2;              // 33792 bytes per h plane
    constexpr int APL = 64 * 40 * 2;               // 5120 per A plane
    constexpr int ABUF = 2 * APL;                  // 10240
    constexpr int SBB1 = KC * SB1 * 2;             // B1 plane bytes (16896)
    constexpr int SBB2 = KC * SB2 * 2;
    constexpr int BUF0 = 2 * HPL;                  // 67584 (stage region)
    constexpr int BUF1 = 0;                        // aliases h planes (phase1)
    constexpr int P2B0 = BUF0;                     // phase2 B2 buffers
    constexpr int P2B1 = BUF0 + 2 * SBB2;

    extern __shared__ char dsm[];
    uint32_t sbase = smem_u32(dsm);

    const int tid = threadIdx.x;
    const int wid = tid >> 5, lane = tid & 31;
    const int wm = wid & 1, wn = wid >> 1;
    const int n0 = blockIdx.x * 64;
    int rem = nRows - n0;
    if (rem > 64) rem = 64;

    const int lrow = lane & 15, lhalf = lane >> 4;
    const int qr = lane >> 2, qc = (lane & 3) << 1;

    // stage A+B1 chunk c into buffer at 'buf'
    auto stage1 = [&](int c, uint32_t buf) {
        const int c0 = c * KC;
        {   // A: 64 rows x 32 cols, both planes (256 x 16B each)
            int row = tid >> 2, j = tid & 3;
            int gr = n0 + (row < rem ? row : rem - 1);
            uint32_t dst = sbase + buf + (uint32_t)(row * 80 + j * 16);
            cpa16(dst, (const char*)(Ah + (size_t)gr * K1 + c0) + j * 16);
            cpa16(dst + APL, (const char*)(Al + (size_t)gr * K1 + c0) + j * 16);
        }
        {   // B1: 32 rows x N1, both planes
            constexpr int G8 = N1 / 8;
            #pragma unroll
            for (int it = 0; it < KC * G8 / 256; it++) {
                int idx = it * 256 + tid;
                int row = idx / G8, g = idx - row * G8;
                uint32_t dst = sbase + buf + ABUF + (uint32_t)(row * (SB1 * 2) + g * 16);
                cpa16(dst, (const char*)(B1h + (size_t)(c0 + row) * N1) + g * 16);
                cpa16(dst + SBB1, (const char*)(B1l + (size_t)(c0 + row) * N1) + g * 16);
            }
        }
        CP_COMMIT();
    };
    auto stage2 = [&](int c, uint32_t buf) {
        const int c0 = c * KC;
        constexpr int G8 = N2 / 8;
        #pragma unroll
        for (int it = 0; it < (KC * G8 + 255) / 256; it++) {
            int idx = it * 256 + tid;
            if (KC * G8 % 256 == 0 || idx < KC * G8) {
                int row = idx / G8, g = idx - row * G8;
                uint32_t dst = sbase + buf + (uint32_t)(row * (SB2 * 2) + g * 16);
                cpa16(dst, (const char*)(B2h + (size_t)(c0 + row) * N2) + g * 16);
                cpa16(dst + SBB2, (const char*)(B2l + (size_t)(c0 + row) * N2) + g * 16);
            }
        }
        CP_COMMIT();
    };

    // =========================== phase 1 ===========================
    {
        const int col0 = wn * WC1;
        float acc[2][NT1][4];
        #pragma unroll
        for (int mt = 0; mt < 2; mt++)
            #pragma unroll
            for (int j = 0; j < NT1; j++)
                #pragma unroll
                for (int q = 0; q < 4; q++) acc[mt][j][q] = 0.f;

        stage1(0, BUF0);
        for (int c = 0; c < NCH1; c++) {
            if (c + 1 < NCH1) {
                stage1(c + 1, (c + 1) & 1 ? BUF1 : BUF0);
                CP_WAIT1();
            } else {
                CP_WAIT0();
            }
            __syncthreads();

            const uint32_t buf = (c & 1) ? BUF1 : BUF0;
            #pragma unroll
            for (int kk = 0; kk < KC; kk += 16) {
                uint32_t ah[2][4], al[2][4];
                #pragma unroll
                for (int mt = 0; mt < 2; mt++) {
                    uint32_t ra = sbase + buf +
                        (uint32_t)((32 * wm + 16 * mt + lrow) * 80 + kk * 2 + lhalf * 16);
                    ldsm_x4(ah[mt], ra);
                    ldsm_x4(al[mt], ra + APL);
                }
                #pragma unroll
                for (int ng = 0; ng < NTG1; ng++) {
                    uint32_t rb = sbase + buf + ABUF +
                        (uint32_t)(((kk + lrow) * SB1 + col0 + ng * 16) * 2 + lhalf * 16);
                    uint32_t bh[4], bl[4];
                    ldsm_x4t(bh, rb);
                    ldsm_x4t(bl, rb + SBB1);
                    #pragma unroll
                    for (int mt = 0; mt < 2; mt++) {
                        mma_bf16(acc[mt][2 * ng],     ah[mt], bh[0], bh[1]);
                        mma_bf16(acc[mt][2 * ng],     ah[mt], bl[0], bl[1]);
                        mma_bf16(acc[mt][2 * ng],     al[mt], bh[0], bh[1]);
                        mma_bf16(acc[mt][2 * ng + 1], ah[mt], bh[2], bh[3]);
                        mma_bf16(acc[mt][2 * ng + 1], ah[mt], bl[2], bl[3]);
                        mma_bf16(acc[mt][2 * ng + 1], al[mt], bh[2], bh[3]);
                    }
                }
            }
            __syncthreads();   // buffer free for restage / epilogue aliasing
        }

        // overlap: issue phase2 chunk 0 stage (BUF0 region is dead now)
        stage2(0, P2B0);

        // epilogue -> h smem planes (relu + split); overwrites BUF1 region
        #pragma unroll
        for (int mt = 0; mt < 2; mt++) {
            int row0 = 32 * wm + 16 * mt + qr;
            #pragma unroll
            for (int j = 0; j < NT1; j++) {
                int col = col0 + 8 * j + qc;
                float b0 = __ldg(&bias1[col]), b1 = __ldg(&bias1[col + 1]);
                float v00 = fmaxf(acc[mt][j][0] + b0, 0.f);
                float v01 = fmaxf(acc[mt][j][1] + b1, 0.f);
                float v10 = fmaxf(acc[mt][j][2] + b0, 0.f);
                float v11 = fmaxf(acc[mt][j][3] + b1, 0.f);
                uint32_t hp, lp;
                uint32_t o0 = (uint32_t)((row0 * HST + col) * 2);
                split_pair(v00, v01, hp, lp);
                *(uint32_t*)(dsm + o0) = hp;
                *(uint32_t*)(dsm + HPL + o0) = lp;
                uint32_t o1 = o0 + (uint32_t)(8 * HST * 2);
                split_pair(v10, v11, hp, lp);
                *(uint32_t*)(dsm + o1) = hp;
                *(uint32_t*)(dsm + HPL + o1) = lp;
            }
        }
    }
    __syncthreads();

    // =========================== phase 2 ===========================
    {
        const int col0 = wn * WC2;
        float acc[2][NT2][4];
        #pragma unroll
        for (int mt = 0; mt < 2; mt++)
            #pragma unroll
            for (int j = 0; j < NT2; j++)
                #pragma unroll
                for (int q = 0; q < 4; q++) acc[mt][j][q] = 0.f;

        for (int c = 0; c < NCH2; c++) {
            if (c + 1 < NCH2) {
                stage2(c + 1, (c + 1) & 1 ? P2B1 : P2B0);
                CP_WAIT1();
            } else {
                CP_WAIT0();
            }
            __syncthreads();

            const uint32_t buf = (c & 1) ? P2B1 : P2B0;
            const int c0 = c * KC;
            #pragma unroll
            for (int kk = 0; kk < KC; kk += 16) {
                uint32_t ah[2][4], al[2][4];
                #pragma unroll
                for (int mt = 0; mt < 2; mt++) {
                    uint32_t ra = sbase +
                        (uint32_t)(((32 * wm + 16 * mt + lrow) * HST + c0 + kk) * 2 + lhalf * 16);
                    ldsm_x4(ah[mt], ra);
                    ldsm_x4(al[mt], ra + HPL);
                }
                #pragma unroll
                for (int ng = 0; ng < NTG2; ng++) {
                    uint32_t rb = sbase + buf +
                        (uint32_t)(((kk + lrow) * SB2 + col0 + ng * 16) * 2 + lhalf * 16);
                    uint32_t bh[4], bl[4];
                    ldsm_x4t(bh, rb);
                    ldsm_x4t(bl, rb + SBB2);
                    #pragma unroll
                    for (int mt = 0; mt < 2; mt++) {
                        mma_bf16(acc[mt][2 * ng],     ah[mt], bh[0], bh[1]);
                        mma_bf16(acc[mt][2 * ng],     ah[mt], bl[0], bl[1]);
                        mma_bf16(acc[mt][2 * ng],     al[mt], bh[0], bh[1]);
                        mma_bf16(acc[mt][2 * ng + 1], ah[mt], bh[2], bh[3]);
                        mma_bf16(acc[mt][2 * ng + 1], ah[mt], bl[2], bl[3]);
                        mma_bf16(acc[mt][2 * ng + 1], al[mt], bh[2], bh[3]);
                    }
                }
            }
            if (c + 1 < NCH2) __syncthreads();
        }

        // epilogue -> global
        #pragma unroll
        for (int mt = 0; mt < 2; mt++) {
            int row0 = 32 * wm + 16 * mt + qr;
            int row1 = row0 + 8;
            #pragma unroll
            for (int j = 0; j < NT2; j++) {
                int col = col0 + 8 * j + qc;
                float b0 = __ldg(&bias2[col]), b1 = __ldg(&bias2[col + 1]);
                float v00 = acc[mt][j][0] + b0, v01 = acc[mt][j][1] + b1;
                float v10 = acc[mt][j][2] + b0, v11 = acc[mt][j][3] + b1;
                if (SPLITOUT2) {
                    uint32_t hp, lp;
                    if (row0 < rem) {
                        size_t o = (size_t)(n0 + row0) * N2 + col;
                        split_pair(v00, v01, hp, lp);
                        *(uint32_t*)(Ch + o) = hp; *(uint32_t*)(Cl + o) = lp;
                    }
                    if (row1 < rem) {
                        size_t o = (size_t)(n0 + row1) * N2 + col;
                        split_pair(v10, v11, hp, lp);
                        *(uint32_t*)(Ch + o) = hp; *(uint32_t*)(Cl + o) = lp;
                    }
                } else {
                    if (row0 < rem)
                        *(float2*)(Cf + (size_t)(n0 + row0) * N2 + col) = make_float2(v00, v01);
                    if (row1 < rem)
                        *(float2*)(Cf + (size_t)(n0 + row1) * N2 + col) = make_float2(v10, v11);
                }
            }
        }
    }
}

// ------------------------------- launcher ----------------------------------
extern "C" void kernel_launch(void* const* d_in, const int* in_sizes, int n_in,
                              void* d_out, int out_size) {
    const float* x   = (const float*)d_in[0];
    const int*   ei  = (const int*)d_in[1];
    const float* c1W = (const float*)d_in[2];
    const float* c1r = (const float*)d_in[3];
    const float* c1b = (const float*)d_in[4];
    const float* c2W = (const float*)d_in[5];
    const float* c2r = (const float*)d_in[6];
    const float* c2b = (const float*)d_in[7];
    const float* dw1 = (const float*)d_in[8];
    const float* db1 = (const float*)d_in[9];
    const float* dw2 = (const float*)d_in[10];
    const float* db2 = (const float*)d_in[11];
    float* out = (float*)d_out;

    void *pB2c;
    void *pA1h, *pA1l, *pWh, *pWl, *pZh, *pZl;
    void *pB1h, *pB1l, *pB2h, *pB2l, *pD1h, *pD1l, *pD2h, *pD2l;
    cudaGetSymbolAddress(&pB2c, g_b2c);
    cudaGetSymbolAddress(&pA1h, g_A1h); cudaGetSymbolAddress(&pA1l, g_A1l);
    cudaGetSymbolAddress(&pWh, g_wh);   cudaGetSymbolAddress(&pWl, g_wl);
    cudaGetSymbolAddress(&pZh, g_zh);   cudaGetSymbolAddress(&pZl, g_zl);
    cudaGetSymbolAddress(&pB1h, g_B1h); cudaGetSymbolAddress(&pB1l, g_B1l);
    cudaGetSymbolAddress(&pB2h, g_B2h); cudaGetSymbolAddress(&pB2l, g_B2l);
    cudaGetSymbolAddress(&pD1h, g_D1h); cudaGetSymbolAddress(&pD1l, g_D1l);
    cudaGetSymbolAddress(&pD2h, g_D2h); cudaGetSymbolAddress(&pD2l, g_D2l);

    // smem: h planes 67584 + stage buf0 (A 10240 + B 33792) = 111616 -> occ 2
    const int SM_F = 67584 + 10240 + 33792;
    cudaFuncSetAttribute(fused2_k<128, 256, 256, 128, true>,
                         cudaFuncAttributeMaxDynamicSharedMemorySize, SM_F);
    cudaFuncSetAttribute(fused2_k<64, 256, 256, 64, false>,
                         cudaFuncAttributeMaxDynamicSharedMemorySize, SM_F);

    const int nFG = (NNODES + 63) / 64;                 // 782
    const int nE4Blocks = (NEDGES / 4 + 255) / 256;     // 782
    const int nAggBlocks = (NNODES * 32 + 255) / 256;   // 6250

    // --- CSR build (g_cnt zero at entry; scanm re-zeroes; place zeroes flags)
    hist_k<<<nE4Blocks, 256>>>(ei);
    scanm_k<<<NB_SCAN, 1024>>>();
    place_k<<<nE4Blocks, 256>>>(ei);

    // --- conv1 input aggregation ---
    agg1_k<<<nAggBlocks, 256>>>(x);
    prep_k<<<128, 256>>>(c1W, c1r, c2W, c2r, c2b, dw1, dw2);

    // --- fused conv1 GEMM + conv2 weight GEMM: A1 -> h(smem) -> hWr ---
    fused2_k<128, 256, 256, 128, true><<<nFG, 256, SM_F>>>(
        (const __nv_bfloat16*)pA1h, (const __nv_bfloat16*)pA1l,
        (const __nv_bfloat16*)pB1h, (const __nv_bfloat16*)pB1l, c1b,
        (const __nv_bfloat16*)pB2h, (const __nv_bfloat16*)pB2l, (const float*)pB2c,
        nullptr, (__nv_bfloat16*)pWh, (__nv_bfloat16*)pWl, NNODES);

    // --- conv2 aggregation -> z ---
    agg2_k<<<nAggBlocks, 256>>>();

    // --- fused decoder: z -> h2(smem) -> out ---
    fused2_k<64, 256, 256, 64, false><<<nFG, 256, SM_F>>>(
        (const __nv_bfloat16*)pZh, (const __nv_bfloat16*)pZl,
        (const __nv_bfloat16*)pD1h, (const __nv_bfloat16*)pD1l, db1,
        (const __nv_bfloat16*)pD2h, (const __nv_bfloat16*)pD2l, db2,
        out, nullptr, nullptr, NNODES);
}

// round 10
// speedup vs baseline: 1.2371x; 1.0247x over previous
#include <cuda_runtime.h>
#include <cuda_bf16.h>
#include <math.h>
#include <stdint.h>

// ---------------------------------------------------------------------------
// GraphAE on GB300 (sm_103 plain target -> mma.sync tensor path).
// pseudo == 0 => only spline weight k=0 contributes.
// Activations as bf16 hi/lo plane pairs (hWr inter-stage tensor as fp32);
// 3-product compensated bf16 MMA (fp32 accum) == fp32-accurate GEMMs.
// Pipeline (8 launches):
//   hist -> scanm -> place -> agg1 -> prep -> FUSED[G1+G2] -> agg2
//   -> FUSED[G3+G4]
// Aggs: half-warp float4 gathers (one LDG.128 warp-instr = two edges).
// ---------------------------------------------------------------------------

#define NNODES 50000
#define NEDGES 800000
#define NB_SCAN 49

// ------------------------- scratch (static device) -------------------------
__device__ int   g_cnt[NNODES];        // zero-init (BSS); scanm restores zero
__device__ int   g_rowptr[NNODES + 1];
__device__ int   g_cursor[NNODES];
__device__ int   g_csr[NEDGES];
__device__ float g_invdeg[NNODES];
__device__ int   g_bflag[NB_SCAN];     // scan aggregates (sentinel +1); place zeroes

// activation planes (bf16 hi/lo) + fp32 hWr
__device__ __nv_bfloat16 g_A1h[(size_t)NNODES * 128], g_A1l[(size_t)NNODES * 128];
__device__ float         g_w[(size_t)NNODES * 128];   // hWr = [h@W2 | h@root2+b2]
__device__ __nv_bfloat16 g_zh[(size_t)NNODES * 64],   g_zl[(size_t)NNODES * 64];

// bf16 hi/lo split weights, natural [k][n] row-major
__device__ __nv_bfloat16 g_B1h[128 * 256], g_B1l[128 * 256];
__device__ __nv_bfloat16 g_B2h[256 * 128], g_B2l[256 * 128];
__device__ __nv_bfloat16 g_D1h[64 * 256],  g_D1l[64 * 256];
__device__ __nv_bfloat16 g_D2h[256 * 64],  g_D2l[256 * 64];
__device__ float g_b2c[128];                   // [0 | conv2_b]

// ------------------------------ helpers ------------------------------------
__device__ __forceinline__ uint32_t smem_u32(const void* p) {
    uint32_t a;
    asm("{ .reg .u64 t; cvta.to.shared.u64 t, %1; cvt.u32.u64 %0, t; }"
        : "=r"(a) : "l"(p));
    return a;
}
__device__ __forceinline__ void ldsm_x4(uint32_t* r, uint32_t addr) {
    asm volatile("ldmatrix.sync.aligned.m8n8.x4.shared.b16 {%0,%1,%2,%3}, [%4];"
                 : "=r"(r[0]), "=r"(r[1]), "=r"(r[2]), "=r"(r[3]) : "r"(addr));
}
__device__ __forceinline__ void ldsm_x4t(uint32_t* r, uint32_t addr) {
    asm volatile("ldmatrix.sync.aligned.m8n8.x4.trans.shared.b16 {%0,%1,%2,%3}, [%4];"
                 : "=r"(r[0]), "=r"(r[1]), "=r"(r[2]), "=r"(r[3]) : "r"(addr));
}
__device__ __forceinline__ void mma_bf16(float* d, const uint32_t* a,
                                         uint32_t b0, uint32_t b1) {
    asm volatile("mma.sync.aligned.m16n8k16.row.col.f32.bf16.bf16.f32 "
                 "{%0,%1,%2,%3}, {%4,%5,%6,%7}, {%8,%9}, {%0,%1,%2,%3};"
                 : "+f"(d[0]), "+f"(d[1]), "+f"(d[2]), "+f"(d[3])
                 : "r"(a[0]), "r"(a[1]), "r"(a[2]), "r"(a[3]), "r"(b0), "r"(b1));
}
__device__ __forceinline__ void cpa16(uint32_t dst, const void* src) {
    asm volatile("cp.async.cg.shared.global [%0], [%1], 16;"
                 :: "r"(dst), "l"(src));
}
#define CP_COMMIT() asm volatile("cp.async.commit_group;" ::: "memory")
#define CP_WAIT0()  asm volatile("cp.async.wait_group 0;" ::: "memory")
#define CP_WAIT1()  asm volatile("cp.async.wait_group 1;" ::: "memory")

__device__ __forceinline__ void split1(float v, uint16_t& h, uint16_t& l) {
    __nv_bfloat16 hb = __float2bfloat16_rn(v);
    float r = v - __bfloat162float(hb);
    __nv_bfloat16 lb = __float2bfloat16_rn(r);
    h = __bfloat16_as_ushort(hb);
    l = __bfloat16_as_ushort(lb);
}
__device__ __forceinline__ void split_pair(float a, float b, uint32_t& hp, uint32_t& lp) {
    uint16_t h0, l0, h1, l1;
    split1(a, h0, l0); split1(b, h1, l1);
    hp = (uint32_t)h0 | ((uint32_t)h1 << 16);
    lp = (uint32_t)l0 | ((uint32_t)l1 << 16);
}

// ------------------------------ weight prep --------------------------------
__global__ void prep_k(const float* __restrict__ c1W, const float* __restrict__ c1r,
                       const float* __restrict__ c2W, const float* __restrict__ c2r,
                       const float* __restrict__ c2b,
                       const float* __restrict__ dw1, const float* __restrict__ dw2) {
    int i = blockIdx.x * blockDim.x + threadIdx.x;
    uint16_t h, l;
    if (i < 128 * 256) {  // B1 [k=128][n=256]
        int k = i >> 8, n = i & 255;
        float v = (k < 64) ? c1W[k * 256 + n] : c1r[(k - 64) * 256 + n];
        split1(v, h, l);
        g_B1h[i] = __ushort_as_bfloat16(h); g_B1l[i] = __ushort_as_bfloat16(l);
    }
    if (i < 256 * 128) {  // B2 [k=256][n=128]
        int k = i >> 7, n = i & 127;
        float v = (n < 64) ? c2W[k * 64 + n] : c2r[k * 64 + (n - 64)];
        split1(v, h, l);
        g_B2h[i] = __ushort_as_bfloat16(h); g_B2l[i] = __ushort_as_bfloat16(l);
    }
    if (i < 64 * 256) {   // D1 [k=64][n=256]
        split1(dw1[i], h, l);
        g_D1h[i] = __ushort_as_bfloat16(h); g_D1l[i] = __ushort_as_bfloat16(l);
    }
    if (i < 256 * 64) {   // D2 [k=256][n=64]
        split1(dw2[i], h, l);
        g_D2h[i] = __ushort_as_bfloat16(h); g_D2l[i] = __ushort_as_bfloat16(l);
    }
    if (i < 128) g_b2c[i] = (i < 64) ? 0.0f : c2b[i - 64];
}

// ------------------------------- CSR build ---------------------------------
__global__ void hist_k(const int* __restrict__ ei) {
    int e4 = (blockIdx.x * blockDim.x + threadIdx.x) * 4;
    if (e4 < NEDGES) {
        int4 d = *(const int4*)(ei + NEDGES + e4);
        atomicAdd(&g_cnt[d.x], 1);
        atomicAdd(&g_cnt[d.y], 1);
        atomicAdd(&g_cnt[d.z], 1);
        atomicAdd(&g_cnt[d.w], 1);
    }
}

// single-pass scan: 49 co-resident blocks, warp-shuffle local scan,
// cross-block offsets via published aggregates (sentinel = sum+1).
// Re-zeroes g_cnt; g_bflag is zeroed by place_k after use.
__global__ void scanm_k() {
    __shared__ int wsum[32];
    __shared__ int s_boff;
    int blk = blockIdx.x, tid = threadIdx.x;
    int i = blk * 1024 + tid;
    int v = (i < NNODES) ? g_cnt[i] : 0;
    int incl = v;
    #pragma unroll
    for (int o = 1; o < 32; o <<= 1) {
        int t = __shfl_up_sync(0xffffffff, incl, o);
        if ((tid & 31) >= o) incl += t;
    }
    if ((tid & 31) == 31) wsum[tid >> 5] = incl;
    if (tid == 0) s_boff = 0;
    __syncthreads();
    if (tid < 32) {
        int w = wsum[tid];
        #pragma unroll
        for (int o = 1; o < 32; o <<= 1) {
            int t = __shfl_up_sync(0xffffffff, w, o);
            if (tid >= o) w += t;
        }
        wsum[tid] = w;                         // inclusive warp sums
    }
    __syncthreads();
    if (tid >= 32) incl += wsum[(tid >> 5) - 1];
    if (tid == 1023) atomicExch(&g_bflag[blk], wsum[31] + 1);  // publish total
    if (tid < blk) {                                           // poll predecessors
        int t;
        do { t = atomicAdd(&g_bflag[tid], 0); } while (t == 0);
        atomicAdd(&s_boff, t - 1);
    }
    __syncthreads();
    int boff = s_boff;
    if (i < NNODES) {
        int start = boff + incl - v;
        g_rowptr[i] = start;
        g_cursor[i] = start;
        g_invdeg[i] = 1.0f / fmaxf((float)v, 1.0f);
        g_cnt[i] = 0;                          // restore for next replay
        if (i == NNODES - 1) g_rowptr[NNODES] = boff + incl;
    }
}

__global__ void place_k(const int* __restrict__ ei) {
    int t = blockIdx.x * blockDim.x + threadIdx.x;
    int e4 = t * 4;
    if (e4 < NEDGES) {
        int4 d = *(const int4*)(ei + NEDGES + e4);
        int4 s = *(const int4*)(ei + e4);
        g_csr[atomicAdd(&g_cursor[d.x], 1)] = s.x;
        g_csr[atomicAdd(&g_cursor[d.y], 1)] = s.y;
        g_csr[atomicAdd(&g_cursor[d.z], 1)] = s.z;
        g_csr[atomicAdd(&g_cursor[d.w], 1)] = s.w;
    }
    if (t < NB_SCAN) g_bflag[t] = 0;           // reset scan flags for next replay
}

// --------------------------- gather aggregations ---------------------------
// warp per node; HALF-warp per edge: 16 lanes x float4 = 256B row, so one
// warp instruction covers two edges. Halves combined via shfl_xor(16).
__global__ void agg1_k(const float* __restrict__ x) {
    int gt = blockIdx.x * blockDim.x + threadIdx.x;
    int node = gt >> 5;
    if (node >= NNODES) return;
    int lane = gt & 31;
    int half = lane >> 4, sub = lane & 15;
    int beg = g_rowptr[node], end = g_rowptr[node + 1];
    float4 s = make_float4(0.f, 0.f, 0.f, 0.f);
    for (int i = beg + half; i < end; i += 2) {
        int src = g_csr[i];
        float4 v = __ldg((const float4*)(x + (size_t)src * 64 + sub * 4));
        s.x += v.x; s.y += v.y; s.z += v.z; s.w += v.w;
    }
    s.x += __shfl_xor_sync(0xffffffff, s.x, 16);
    s.y += __shfl_xor_sync(0xffffffff, s.y, 16);
    s.z += __shfl_xor_sync(0xffffffff, s.z, 16);
    s.w += __shfl_xor_sync(0xffffffff, s.w, 16);
    float iv = g_invdeg[node];
    size_t o = (size_t)node * 128 + sub * 4;
    uint32_t hp0, lp0, hp1, lp1;
    if (half == 0) {
        split_pair(s.x * iv, s.y * iv, hp0, lp0);
        split_pair(s.z * iv, s.w * iv, hp1, lp1);
        *(uint2*)(g_A1h + o) = make_uint2(hp0, hp1);
        *(uint2*)(g_A1l + o) = make_uint2(lp0, lp1);
    } else {
        float4 xv = __ldg((const float4*)(x + (size_t)node * 64 + sub * 4));
        split_pair(xv.x, xv.y, hp0, lp0);
        split_pair(xv.z, xv.w, hp1, lp1);
        *(uint2*)(g_A1h + o + 64) = make_uint2(hp0, hp1);
        *(uint2*)(g_A1l + o + 64) = make_uint2(lp0, lp1);
    }
}

// z = gather(hW)*invdeg + hroot; hWr fp32: hW = cols 0:64, hroot = 64:128.
__global__ void agg2_k() {
    int gt = blockIdx.x * blockDim.x + threadIdx.x;
    int node = gt >> 5;
    if (node >= NNODES) return;
    int lane = gt & 31;
    int half = lane >> 4, sub = lane & 15;
    int beg = g_rowptr[node], end = g_rowptr[node + 1];
    float4 s = make_float4(0.f, 0.f, 0.f, 0.f);
    for (int i = beg + half; i < end; i += 2) {
        int src = g_csr[i];
        float4 v = __ldg((const float4*)(g_w + (size_t)src * 128 + sub * 4));
        s.x += v.x; s.y += v.y; s.z += v.z; s.w += v.w;
    }
    s.x += __shfl_xor_sync(0xffffffff, s.x, 16);
    s.y += __shfl_xor_sync(0xffffffff, s.y, 16);
    s.z += __shfl_xor_sync(0xffffffff, s.z, 16);
    s.w += __shfl_xor_sync(0xffffffff, s.w, 16);
    float iv = g_invdeg[node];
    float4 r = __ldg((const float4*)(g_w + (size_t)node * 128 + 64 + sub * 4));
    float z0 = s.x * iv + r.x, z1 = s.y * iv + r.y;
    float z2 = s.z * iv + r.z, z3 = s.w * iv + r.w;
    uint32_t hp0, lp0, hp1, lp1;
    split_pair(z0, z1, hp0, lp0);
    split_pair(z2, z3, hp1, lp1);
    size_t zo = (size_t)node * 64 + sub * 4;
    if (half == 0) *(uint2*)(g_zh + zo) = make_uint2(hp0, hp1);
    else           *(uint2*)(g_zl + zo) = make_uint2(lp0, lp1);
}

// -------------------- fused two-GEMM kernel (64-row tile) ------------------
// Phase1: T = relu(A[64,K1] @ B1[K1,N1=256] + bias1) -> split -> h smem
// Phase2: out = T @ B2[K2=N1,N2] + bias2 -> fp32 (g_w or final out)
// Double-buffered stages: phase1 buf1 aliases the (then-dead) h region; the
// last phase1 chunk is odd -> lives in buf1, dead exactly when the epilogue
// overwrites it. Phase2 double-buffers B2 in the dead phase1 stage region.
// 8 warps as 2(m) x 4(n); warp tile = 32 rows x N/4 cols. 3-product MMA.
template <int K1, int N1, int K2, int N2>
__global__ void __launch_bounds__(256, 2)
fused2_k(const __nv_bfloat16* __restrict__ Ah, const __nv_bfloat16* __restrict__ Al,
         const __nv_bfloat16* __restrict__ B1h, const __nv_bfloat16* __restrict__ B1l,
         const float* __restrict__ bias1,
         const __nv_bfloat16* __restrict__ B2h, const __nv_bfloat16* __restrict__ B2l,
         const float* __restrict__ bias2,
         float* __restrict__ Cf, int nRows) {
    static_assert(N1 == 256 && K2 == N1, "layout assumes N1=256");
    constexpr int KC = 32;
    constexpr int NCH1 = K1 / KC, NCH2 = K2 / KC;
    static_assert(NCH1 % 2 == 0, "last phase1 chunk must land in buf1");
    constexpr int WC1 = N1 / 4, NT1 = WC1 / 8, NTG1 = WC1 / 16;
    constexpr int WC2 = N2 / 4, NT2 = WC2 / 8, NTG2 = WC2 / 16;
    constexpr int SB1 = N1 + 8, SB2 = N2 + 8;
    constexpr int HST = 264;                       // h smem row stride (elems)
    constexpr int HPL = 64 * HST * 2;              // 33792 bytes per h plane
    constexpr int APL = 64 * 40 * 2;               // 5120 per A plane
    constexpr int ABUF = 2 * APL;                  // 10240
    constexpr int SBB1 = KC * SB1 * 2;             // B1 plane bytes (16896)
    constexpr int SBB2 = KC * SB2 * 2;
    constexpr int BUF0 = 2 * HPL;                  // 67584 (stage region)
    constexpr int BUF1 = 0;                        // aliases h planes (phase1)
    constexpr int P2B0 = BUF0;                     // phase2 B2 buffers
    constexpr int P2B1 = BUF0 + 2 * SBB2;

    extern __shared__ char dsm[];
    uint32_t sbase = smem_u32(dsm);

    const int tid = threadIdx.x;
    const int wid = tid >> 5, lane = tid & 31;
    const int wm = wid & 1, wn = wid >> 1;
    const int n0 = blockIdx.x * 64;
    int rem = nRows - n0;
    if (rem > 64) rem = 64;

    const int lrow = lane & 15, lhalf = lane >> 4;
    const int qr = lane >> 2, qc = (lane & 3) << 1;

    // stage A+B1 chunk c into buffer at 'buf'
    auto stage1 = [&](int c, uint32_t buf) {
        const int c0 = c * KC;
        {   // A: 64 rows x 32 cols, both planes (256 x 16B each)
            int row = tid >> 2, j = tid & 3;
            int gr = n0 + (row < rem ? row : rem - 1);
            uint32_t dst = sbase + buf + (uint32_t)(row * 80 + j * 16);
            cpa16(dst, (const char*)(Ah + (size_t)gr * K1 + c0) + j * 16);
            cpa16(dst + APL, (const char*)(Al + (size_t)gr * K1 + c0) + j * 16);
        }
        {   // B1: 32 rows x N1, both planes
            constexpr int G8 = N1 / 8;
            #pragma unroll
            for (int it = 0; it < KC * G8 / 256; it++) {
                int idx = it * 256 + tid;
                int row = idx / G8, g = idx - row * G8;
                uint32_t dst = sbase + buf + ABUF + (uint32_t)(row * (SB1 * 2) + g * 16);
                cpa16(dst, (const char*)(B1h + (size_t)(c0 + row) * N1) + g * 16);
                cpa16(dst + SBB1, (const char*)(B1l + (size_t)(c0 + row) * N1) + g * 16);
            }
        }
        CP_COMMIT();
    };
    auto stage2 = [&](int c, uint32_t buf) {
        const int c0 = c * KC;
        constexpr int G8 = N2 / 8;
        #pragma unroll
        for (int it = 0; it < (KC * G8 + 255) / 256; it++) {
            int idx = it * 256 + tid;
            if (KC * G8 % 256 == 0 || idx < KC * G8) {
                int row = idx / G8, g = idx - row * G8;
                uint32_t dst = sbase + buf + (uint32_t)(row * (SB2 * 2) + g * 16);
                cpa16(dst, (const char*)(B2h + (size_t)(c0 + row) * N2) + g * 16);
                cpa16(dst + SBB2, (const char*)(B2l + (size_t)(c0 + row) * N2) + g * 16);
            }
        }
        CP_COMMIT();
    };

    // =========================== phase 1 ===========================
    {
        const int col0 = wn * WC1;
        float acc[2][NT1][4];
        #pragma unroll
        for (int mt = 0; mt < 2; mt++)
            #pragma unroll
            for (int j = 0; j < NT1; j++)
                #pragma unroll
                for (int q = 0; q < 4; q++) acc[mt][j][q] = 0.f;

        stage1(0, BUF0);
        for (int c = 0; c < NCH1; c++) {
            if (c + 1 < NCH1) {
                stage1(c + 1, (c + 1) & 1 ? BUF1 : BUF0);
                CP_WAIT1();
            } else {
                CP_WAIT0();
            }
            __syncthreads();

            const uint32_t buf = (c & 1) ? BUF1 : BUF0;
            #pragma unroll
            for (int kk = 0; kk < KC; kk += 16) {
                uint32_t ah[2][4], al[2][4];
                #pragma unroll
                for (int mt = 0; mt < 2; mt++) {
                    uint32_t ra = sbase + buf +
                        (uint32_t)((32 * wm + 16 * mt + lrow) * 80 + kk * 2 + lhalf * 16);
                    ldsm_x4(ah[mt], ra);
                    ldsm_x4(al[mt], ra + APL);
                }
                #pragma unroll
                for (int ng = 0; ng < NTG1; ng++) {
                    uint32_t rb = sbase + buf + ABUF +
                        (uint32_t)(((kk + lrow) * SB1 + col0 + ng * 16) * 2 + lhalf * 16);
                    uint32_t bh[4], bl[4];
                    ldsm_x4t(bh, rb);
                    ldsm_x4t(bl, rb + SBB1);
                    #pragma unroll
                    for (int mt = 0; mt < 2; mt++) {
                        mma_bf16(acc[mt][2 * ng],     ah[mt], bh[0], bh[1]);
                        mma_bf16(acc[mt][2 * ng],     ah[mt], bl[0], bl[1]);
                        mma_bf16(acc[mt][2 * ng],     al[mt], bh[0], bh[1]);
                        mma_bf16(acc[mt][2 * ng + 1], ah[mt], bh[2], bh[3]);
                        mma_bf16(acc[mt][2 * ng + 1], ah[mt], bl[2], bl[3]);
                        mma_bf16(acc[mt][2 * ng + 1], al[mt], bh[2], bh[3]);
                    }
                }
            }
            __syncthreads();   // buffer free for restage / epilogue aliasing
        }

        // overlap: issue phase2 chunk 0 stage (BUF0 region is dead now)
        stage2(0, P2B0);

        // epilogue -> h smem planes (relu + split); overwrites BUF1 region
        #pragma unroll
        for (int mt = 0; mt < 2; mt++) {
            int row0 = 32 * wm + 16 * mt + qr;
            #pragma unroll
            for (int j = 0; j < NT1; j++) {
                int col = col0 + 8 * j + qc;
                float b0 = __ldg(&bias1[col]), b1 = __ldg(&bias1[col + 1]);
                float v00 = fmaxf(acc[mt][j][0] + b0, 0.f);
                float v01 = fmaxf(acc[mt][j][1] + b1, 0.f);
                float v10 = fmaxf(acc[mt][j][2] + b0, 0.f);
                float v11 = fmaxf(acc[mt][j][3] + b1, 0.f);
                uint32_t hp, lp;
                uint32_t o0 = (uint32_t)((row0 * HST + col) * 2);
                split_pair(v00, v01, hp, lp);
                *(uint32_t*)(dsm + o0) = hp;
                *(uint32_t*)(dsm + HPL + o0) = lp;
                uint32_t o1 = o0 + (uint32_t)(8 * HST * 2);
                split_pair(v10, v11, hp, lp);
                *(uint32_t*)(dsm + o1) = hp;
                *(uint32_t*)(dsm + HPL + o1) = lp;
            }
        }
    }
    __syncthreads();

    // =========================== phase 2 ===========================
    {
        const int col0 = wn * WC2;
        float acc[2][NT2][4];
        #pragma unroll
        for (int mt = 0; mt < 2; mt++)
            #pragma unroll
            for (int j = 0; j < NT2; j++)
                #pragma unroll
                for (int q = 0; q < 4; q++) acc[mt][j][q] = 0.f;

        for (int c = 0; c < NCH2; c++) {
            if (c + 1 < NCH2) {
                stage2(c + 1, (c + 1) & 1 ? P2B1 : P2B0);
                CP_WAIT1();
            } else {
                CP_WAIT0();
            }
            __syncthreads();

            const uint32_t buf = (c & 1) ? P2B1 : P2B0;
            const int c0 = c * KC;
            #pragma unroll
            for (int kk = 0; kk < KC; kk += 16) {
                uint32_t ah[2][4], al[2][4];
                #pragma unroll
                for (int mt = 0; mt < 2; mt++) {
                    uint32_t ra = sbase +
                        (uint32_t)(((32 * wm + 16 * mt + lrow) * HST + c0 + kk) * 2 + lhalf * 16);
                    ldsm_x4(ah[mt], ra);
                    ldsm_x4(al[mt], ra + HPL);
                }
                #pragma unroll
                for (int ng = 0; ng < NTG2; ng++) {
                    uint32_t rb = sbase + buf +
                        (uint32_t)(((kk + lrow) * SB2 + col0 + ng * 16) * 2 + lhalf * 16);
                    uint32_t bh[4], bl[4];
                    ldsm_x4t(bh, rb);
                    ldsm_x4t(bl, rb + SBB2);
                    #pragma unroll
                    for (int mt = 0; mt < 2; mt++) {
                        mma_bf16(acc[mt][2 * ng],     ah[mt], bh[0], bh[1]);
                        mma_bf16(acc[mt][2 * ng],     ah[mt], bl[0], bl[1]);
                        mma_bf16(acc[mt][2 * ng],     al[mt], bh[0], bh[1]);
                        mma_bf16(acc[mt][2 * ng + 1], ah[mt], bh[2], bh[3]);
                        mma_bf16(acc[mt][2 * ng + 1], ah[mt], bl[2], bl[3]);
                        mma_bf16(acc[mt][2 * ng + 1], al[mt], bh[2], bh[3]);
                    }
                }
            }
            if (c + 1 < NCH2) __syncthreads();
        }

        // epilogue -> global fp32
        #pragma unroll
        for (int mt = 0; mt < 2; mt++) {
            int row0 = 32 * wm + 16 * mt + qr;
            int row1 = row0 + 8;
            #pragma unroll
            for (int j = 0; j < NT2; j++) {
                int col = col0 + 8 * j + qc;
                float b0 = __ldg(&bias2[col]), b1 = __ldg(&bias2[col + 1]);
                float v00 = acc[mt][j][0] + b0, v01 = acc[mt][j][1] + b1;
                float v10 = acc[mt][j][2] + b0, v11 = acc[mt][j][3] + b1;
                if (row0 < rem)
                    *(float2*)(Cf + (size_t)(n0 + row0) * N2 + col) = make_float2(v00, v01);
                if (row1 < rem)
                    *(float2*)(Cf + (size_t)(n0 + row1) * N2 + col) = make_float2(v10, v11);
            }
        }
    }
}

// ------------------------------- launcher ----------------------------------
extern "C" void kernel_launch(void* const* d_in, const int* in_sizes, int n_in,
                              void* d_out, int out_size) {
    const float* x   = (const float*)d_in[0];
    const int*   ei  = (const int*)d_in[1];
    const float* c1W = (const float*)d_in[2];
    const float* c1r = (const float*)d_in[3];
    const float* c1b = (const float*)d_in[4];
    const float* c2W = (const float*)d_in[5];
    const float* c2r = (const float*)d_in[6];
    const float* c2b = (const float*)d_in[7];
    const float* dw1 = (const float*)d_in[8];
    const float* db1 = (const float*)d_in[9];
    const float* dw2 = (const float*)d_in[10];
    const float* db2 = (const float*)d_in[11];
    float* out = (float*)d_out;

    void *pB2c, *pW;
    void *pA1h, *pA1l, *pZh, *pZl;
    void *pB1h, *pB1l, *pB2h, *pB2l, *pD1h, *pD1l, *pD2h, *pD2l;
    cudaGetSymbolAddress(&pB2c, g_b2c);
    cudaGetSymbolAddress(&pW, g_w);
    cudaGetSymbolAddress(&pA1h, g_A1h); cudaGetSymbolAddress(&pA1l, g_A1l);
    cudaGetSymbolAddress(&pZh, g_zh);   cudaGetSymbolAddress(&pZl, g_zl);
    cudaGetSymbolAddress(&pB1h, g_B1h); cudaGetSymbolAddress(&pB1l, g_B1l);
    cudaGetSymbolAddress(&pB2h, g_B2h); cudaGetSymbolAddress(&pB2l, g_B2l);
    cudaGetSymbolAddress(&pD1h, g_D1h); cudaGetSymbolAddress(&pD1l, g_D1l);
    cudaGetSymbolAddress(&pD2h, g_D2h); cudaGetSymbolAddress(&pD2l, g_D2l);

    // smem: h planes 67584 + stage buf0 (A 10240 + B 33792) = 111616 -> occ 2
    const int SM_F = 67584 + 10240 + 33792;
    cudaFuncSetAttribute(fused2_k<128, 256, 256, 128>,
                         cudaFuncAttributeMaxDynamicSharedMemorySize, SM_F);
    cudaFuncSetAttribute(fused2_k<64, 256, 256, 64>,
                         cudaFuncAttributeMaxDynamicSharedMemorySize, SM_F);

    const int nFG = (NNODES + 63) / 64;                 // 782
    const int nE4Blocks = (NEDGES / 4 + 255) / 256;     // 782
    const int nAggBlocks = (NNODES * 32 + 255) / 256;   // 6250

    // --- CSR build (g_cnt zero at entry; scanm re-zeroes; place zeroes flags)
    hist_k<<<nE4Blocks, 256>>>(ei);
    scanm_k<<<NB_SCAN, 1024>>>();
    place_k<<<nE4Blocks, 256>>>(ei);

    // --- conv1 input aggregation ---
    agg1_k<<<nAggBlocks, 256>>>(x);
    prep_k<<<128, 256>>>(c1W, c1r, c2W, c2r, c2b, dw1, dw2);

    // --- fused conv1 GEMM + conv2 weight GEMM: A1 -> h(smem) -> hWr (fp32) ---
    fused2_k<128, 256, 256, 128><<<nFG, 256, SM_F>>>(
        (const __nv_bfloat16*)pA1h, (const __nv_bfloat16*)pA1l,
        (const __nv_bfloat16*)pB1h, (const __nv_bfloat16*)pB1l, c1b,
        (const __nv_bfloat16*)pB2h, (const __nv_bfloat16*)pB2l, (const float*)pB2c,
        (float*)pW, NNODES);

    // --- conv2 aggregation -> z planes ---
    agg2_k<<<nAggBlocks, 256>>>();

    // --- fused decoder: z -> h2(smem) -> out ---
    fused2_k<64, 256, 256, 64><<<nFG, 256, SM_F>>>(
        (const __nv_bfloat16*)pZh, (const __nv_bfloat16*)pZl,
        (const __nv_bfloat16*)pD1h, (const __nv_bfloat16*)pD1l, db1,
        (const __nv_bfloat16*)pD2h, (const __nv_bfloat16*)pD2l, db2,
        out, NNODES);
}

// round 11
// speedup vs baseline: 1.3275x; 1.0731x over previous
#include <cuda_runtime.h>
#include <cuda_bf16.h>
#include <math.h>
#include <stdint.h>

// ---------------------------------------------------------------------------
// GraphAE on GB300 (sm_103 plain target -> mma.sync tensor path).
// pseudo == 0 => only spline weight k=0 contributes.
// Activations as bf16 hi/lo plane pairs (hWr inter-stage tensor as fp32);
// 3-product compensated bf16 MMA (fp32 accum) == fp32-accurate GEMMs.
// Pipeline (7 launches):
//   hist+prep -> scanm -> place -> agg1 -> FUSED[G1+G2] -> agg2
//   -> FUSED[G3+G4]
// ---------------------------------------------------------------------------

#define NNODES 50000
#define NEDGES 800000
#define NB_SCAN 49
#define NHIST_BLK 782          // blocks doing histogram (4 edges/thread)
#define NPREP_BLK 128          // blocks doing weight prep

// ------------------------- scratch (static device) -------------------------
__device__ int   g_cnt[NNODES];        // zero-init (BSS); scanm restores zero
__device__ int   g_rowptr[NNODES + 1];
__device__ int   g_cursor[NNODES];
__device__ int   g_csr[NEDGES];
__device__ float g_invdeg[NNODES];
__device__ int   g_bflag[NB_SCAN];     // scan aggregates (sentinel +1); place zeroes

// activation planes (bf16 hi/lo) + fp32 hWr
__device__ __nv_bfloat16 g_A1h[(size_t)NNODES * 128], g_A1l[(size_t)NNODES * 128];
__device__ float         g_w[(size_t)NNODES * 128];   // hWr = [h@W2 | h@root2+b2]
__device__ __nv_bfloat16 g_zh[(size_t)NNODES * 64],   g_zl[(size_t)NNODES * 64];

// bf16 hi/lo split weights, natural [k][n] row-major
__device__ __nv_bfloat16 g_B1h[128 * 256], g_B1l[128 * 256];
__device__ __nv_bfloat16 g_B2h[256 * 128], g_B2l[256 * 128];
__device__ __nv_bfloat16 g_D1h[64 * 256],  g_D1l[64 * 256];
__device__ __nv_bfloat16 g_D2h[256 * 64],  g_D2l[256 * 64];
__device__ float g_b2c[128];                   // [0 | conv2_b]

// ------------------------------ helpers ------------------------------------
__device__ __forceinline__ uint32_t smem_u32(const void* p) {
    uint32_t a;
    asm("{ .reg .u64 t; cvta.to.shared.u64 t, %1; cvt.u32.u64 %0, t; }"
        : "=r"(a) : "l"(p));
    return a;
}
__device__ __forceinline__ void ldsm_x4(uint32_t* r, uint32_t addr) {
    asm volatile("ldmatrix.sync.aligned.m8n8.x4.shared.b16 {%0,%1,%2,%3}, [%4];"
                 : "=r"(r[0]), "=r"(r[1]), "=r"(r[2]), "=r"(r[3]) : "r"(addr));
}
__device__ __forceinline__ void ldsm_x4t(uint32_t* r, uint32_t addr) {
    asm volatile("ldmatrix.sync.aligned.m8n8.x4.trans.shared.b16 {%0,%1,%2,%3}, [%4];"
                 : "=r"(r[0]), "=r"(r[1]), "=r"(r[2]), "=r"(r[3]) : "r"(addr));
}
__device__ __forceinline__ void mma_bf16(float* d, const uint32_t* a,
                                         uint32_t b0, uint32_t b1) {
    asm volatile("mma.sync.aligned.m16n8k16.row.col.f32.bf16.bf16.f32 "
                 "{%0,%1,%2,%3}, {%4,%5,%6,%7}, {%8,%9}, {%0,%1,%2,%3};"
                 : "+f"(d[0]), "+f"(d[1]), "+f"(d[2]), "+f"(d[3])
                 : "r"(a[0]), "r"(a[1]), "r"(a[2]), "r"(a[3]), "r"(b0), "r"(b1));
}
__device__ __forceinline__ void cpa16(uint32_t dst, const void* src) {
    asm volatile("cp.async.cg.shared.global [%0], [%1], 16;"
                 :: "r"(dst), "l"(src));
}
#define CP_COMMIT() asm volatile("cp.async.commit_group;" ::: "memory")
#define CP_WAIT0()  asm volatile("cp.async.wait_group 0;" ::: "memory")
#define CP_WAIT1()  asm volatile("cp.async.wait_group 1;" ::: "memory")

__device__ __forceinline__ void split1(float v, uint16_t& h, uint16_t& l) {
    __nv_bfloat16 hb = __float2bfloat16_rn(v);
    float r = v - __bfloat162float(hb);
    __nv_bfloat16 lb = __float2bfloat16_rn(r);
    h = __bfloat16_as_ushort(hb);
    l = __bfloat16_as_ushort(lb);
}
__device__ __forceinline__ void split_pair(float a, float b, uint32_t& hp, uint32_t& lp) {
    uint16_t h0, l0, h1, l1;
    split1(a, h0, l0); split1(b, h1, l1);
    hp = (uint32_t)h0 | ((uint32_t)h1 << 16);
    lp = (uint32_t)l0 | ((uint32_t)l1 << 16);
}

// --------------------- fused histogram + weight prep -----------------------
__global__ void histprep_k(const int* __restrict__ ei,
                           const float* __restrict__ c1W, const float* __restrict__ c1r,
                           const float* __restrict__ c2W, const float* __restrict__ c2r,
                           const float* __restrict__ c2b,
                           const float* __restrict__ dw1, const float* __restrict__ dw2) {
    if (blockIdx.x < NHIST_BLK) {
        int e4 = (blockIdx.x * blockDim.x + threadIdx.x) * 4;
        if (e4 < NEDGES) {
            int4 d = *(const int4*)(ei + NEDGES + e4);
            atomicAdd(&g_cnt[d.x], 1);
            atomicAdd(&g_cnt[d.y], 1);
            atomicAdd(&g_cnt[d.z], 1);
            atomicAdd(&g_cnt[d.w], 1);
        }
        return;
    }
    int i = (blockIdx.x - NHIST_BLK) * blockDim.x + threadIdx.x;
    uint16_t h, l;
    if (i < 128 * 256) {  // B1 [k=128][n=256]
        int k = i >> 8, n = i & 255;
        float v = (k < 64) ? c1W[k * 256 + n] : c1r[(k - 64) * 256 + n];
        split1(v, h, l);
        g_B1h[i] = __ushort_as_bfloat16(h); g_B1l[i] = __ushort_as_bfloat16(l);
    }
    if (i < 256 * 128) {  // B2 [k=256][n=128]
        int k = i >> 7, n = i & 127;
        float v = (n < 64) ? c2W[k * 64 + n] : c2r[k * 64 + (n - 64)];
        split1(v, h, l);
        g_B2h[i] = __ushort_as_bfloat16(h); g_B2l[i] = __ushort_as_bfloat16(l);
    }
    if (i < 64 * 256) {   // D1 [k=64][n=256]
        split1(dw1[i], h, l);
        g_D1h[i] = __ushort_as_bfloat16(h); g_D1l[i] = __ushort_as_bfloat16(l);
    }
    if (i < 256 * 64) {   // D2 [k=256][n=64]
        split1(dw2[i], h, l);
        g_D2h[i] = __ushort_as_bfloat16(h); g_D2l[i] = __ushort_as_bfloat16(l);
    }
    if (i < 128) g_b2c[i] = (i < 64) ? 0.0f : c2b[i - 64];
}

// ------------------------------- CSR build ---------------------------------
// single-pass scan: 49 co-resident blocks, warp-shuffle local scan,
// cross-block offsets via published aggregates (sentinel = sum+1).
// Re-zeroes g_cnt; g_bflag is zeroed by place_k after use.
__global__ void scanm_k() {
    __shared__ int wsum[32];
    __shared__ int s_boff;
    int blk = blockIdx.x, tid = threadIdx.x;
    int i = blk * 1024 + tid;
    int v = (i < NNODES) ? g_cnt[i] : 0;
    int incl = v;
    #pragma unroll
    for (int o = 1; o < 32; o <<= 1) {
        int t = __shfl_up_sync(0xffffffff, incl, o);
        if ((tid & 31) >= o) incl += t;
    }
    if ((tid & 31) == 31) wsum[tid >> 5] = incl;
    if (tid == 0) s_boff = 0;
    __syncthreads();
    if (tid < 32) {
        int w = wsum[tid];
        #pragma unroll
        for (int o = 1; o < 32; o <<= 1) {
            int t = __shfl_up_sync(0xffffffff, w, o);
            if (tid >= o) w += t;
        }
        wsum[tid] = w;                         // inclusive warp sums
    }
    __syncthreads();
    if (tid >= 32) incl += wsum[(tid >> 5) - 1];
    if (tid == 1023) atomicExch(&g_bflag[blk], wsum[31] + 1);  // publish total
    if (tid < blk) {                                           // poll predecessors
        int t;
        do { t = atomicAdd(&g_bflag[tid], 0); } while (t == 0);
        atomicAdd(&s_boff, t - 1);
    }
    __syncthreads();
    int boff = s_boff;
    if (i < NNODES) {
        int start = boff + incl - v;
        g_rowptr[i] = start;
        g_cursor[i] = start;
        g_invdeg[i] = 1.0f / fmaxf((float)v, 1.0f);
        g_cnt[i] = 0;                          // restore for next replay
        if (i == NNODES - 1) g_rowptr[NNODES] = boff + incl;
    }
}

__global__ void place_k(const int* __restrict__ ei) {
    int t = blockIdx.x * blockDim.x + threadIdx.x;
    int e4 = t * 4;
    if (e4 < NEDGES) {
        int4 d = *(const int4*)(ei + NEDGES + e4);
        int4 s = *(const int4*)(ei + e4);
        g_csr[atomicAdd(&g_cursor[d.x], 1)] = s.x;
        g_csr[atomicAdd(&g_cursor[d.y], 1)] = s.y;
        g_csr[atomicAdd(&g_cursor[d.z], 1)] = s.z;
        g_csr[atomicAdd(&g_cursor[d.w], 1)] = s.w;
    }
    if (t < NB_SCAN) g_bflag[t] = 0;           // reset scan flags for next replay
}

// --------------------------- gather aggregations ---------------------------
// warp per node; lane owns feature pair (2*lane, 2*lane+1); simple loop
// (R8-measured best: unrolling/half-warp variants regressed).
__global__ void agg1_k(const float* __restrict__ x) {
    int gt = blockIdx.x * blockDim.x + threadIdx.x;
    int node = gt >> 5;
    if (node >= NNODES) return;
    int lane = gt & 31;
    int beg = g_rowptr[node], end = g_rowptr[node + 1];
    float s0 = 0.f, s1 = 0.f;
    for (int i = beg; i < end; i++) {
        int s = g_csr[i];
        float2 v = __ldg((const float2*)(x + (size_t)s * 64 + 2 * lane));
        s0 += v.x; s1 += v.y;
    }
    float iv = g_invdeg[node];
    float2 xv = __ldg((const float2*)(x + (size_t)node * 64 + 2 * lane));
    uint32_t hp, lp;
    size_t o = (size_t)node * 128 + 2 * lane;
    split_pair(s0 * iv, s1 * iv, hp, lp);
    *(uint32_t*)(g_A1h + o) = hp; *(uint32_t*)(g_A1l + o) = lp;
    split_pair(xv.x, xv.y, hp, lp);
    *(uint32_t*)(g_A1h + o + 64) = hp; *(uint32_t*)(g_A1l + o + 64) = lp;
}

// z = gather(hW)*invdeg + hroot; hWr fp32: hW = cols 0:64, hroot = 64:128.
__global__ void agg2_k() {
    int gt = blockIdx.x * blockDim.x + threadIdx.x;
    int node = gt >> 5;
    if (node >= NNODES) return;
    int lane = gt & 31;
    int beg = g_rowptr[node], end = g_rowptr[node + 1];
    float s0 = 0.f, s1 = 0.f;
    for (int i = beg; i < end; i++) {
        int s = g_csr[i];
        float2 v = __ldg((const float2*)(g_w + (size_t)s * 128 + 2 * lane));
        s0 += v.x; s1 += v.y;
    }
    float iv = g_invdeg[node];
    float2 r = __ldg((const float2*)(g_w + (size_t)node * 128 + 64 + 2 * lane));
    float z0 = s0 * iv + r.x;
    float z1 = s1 * iv + r.y;
    uint32_t hp, lp;
    split_pair(z0, z1, hp, lp);
    size_t zo = (size_t)node * 64 + 2 * lane;
    *(uint32_t*)(g_zh + zo) = hp; *(uint32_t*)(g_zl + zo) = lp;
}

// -------------------- fused two-GEMM kernel (64-row tile) ------------------
// Phase1: T = relu(A[64,K1] @ B1[K1,N1=256] + bias1) -> split -> h smem
// Phase2: out = T @ B2[K2=N1,N2] + bias2 -> fp32 (g_w or final out)
// Double-buffered stages: phase1 buf1 aliases the (then-dead) h region; the
// last phase1 chunk is odd -> lives in buf1, dead exactly when the epilogue
// overwrites it. Phase2 double-buffers B2 in the dead phase1 stage region.
// 8 warps as 2(m) x 4(n); warp tile = 32 rows x N/4 cols. 3-product MMA.
template <int K1, int N1, int K2, int N2>
__global__ void __launch_bounds__(256, 2)
fused2_k(const __nv_bfloat16* __restrict__ Ah, const __nv_bfloat16* __restrict__ Al,
         const __nv_bfloat16* __restrict__ B1h, const __nv_bfloat16* __restrict__ B1l,
         const float* __restrict__ bias1,
         const __nv_bfloat16* __restrict__ B2h, const __nv_bfloat16* __restrict__ B2l,
         const float* __restrict__ bias2,
         float* __restrict__ Cf, int nRows) {
    static_assert(N1 == 256 && K2 == N1, "layout assumes N1=256");
    constexpr int KC = 32;
    constexpr int NCH1 = K1 / KC, NCH2 = K2 / KC;
    static_assert(NCH1 % 2 == 0, "last phase1 chunk must land in buf1");
    constexpr int WC1 = N1 / 4, NT1 = WC1 / 8, NTG1 = WC1 / 16;
    constexpr int WC2 = N2 / 4, NT2 = WC2 / 8, NTG2 = WC2 / 16;
    constexpr int SB1 = N1 + 8, SB2 = N2 + 8;
    constexpr int HST = 264;                       // h smem row stride (elems)
    constexpr int HPL = 64 * HST * 2;              // 33792 bytes per h plane
    constexpr int APL = 64 * 40 * 2;               // 5120 per A plane
    constexpr int ABUF = 2 * APL;                  // 10240
    constexpr int SBB1 = KC * SB1 * 2;             // B1 plane bytes (16896)
    constexpr int SBB2 = KC * SB2 * 2;
    constexpr int BUF0 = 2 * HPL;                  // 67584 (stage region)
    constexpr int BUF1 = 0;                        // aliases h planes (phase1)
    constexpr int P2B0 = BUF0;                     // phase2 B2 buffers
    constexpr int P2B1 = BUF0 + 2 * SBB2;

    extern __shared__ char dsm[];
    uint32_t sbase = smem_u32(dsm);

    const int tid = threadIdx.x;
    const int wid = tid >> 5, lane = tid & 31;
    const int wm = wid & 1, wn = wid >> 1;
    const int n0 = blockIdx.x * 64;
    int rem = nRows - n0;
    if (rem > 64) rem = 64;

    const int lrow = lane & 15, lhalf = lane >> 4;
    const int qr = lane >> 2, qc = (lane & 3) << 1;

    // stage A+B1 chunk c into buffer at 'buf'
    auto stage1 = [&](int c, uint32_t buf) {
        const int c0 = c * KC;
        {   // A: 64 rows x 32 cols, both planes (256 x 16B each)
            int row = tid >> 2, j = tid & 3;
            int gr = n0 + (row < rem ? row : rem - 1);
            uint32_t dst = sbase + buf + (uint32_t)(row * 80 + j * 16);
            cpa16(dst, (const char*)(Ah + (size_t)gr * K1 + c0) + j * 16);
            cpa16(dst + APL, (const char*)(Al + (size_t)gr * K1 + c0) + j * 16);
        }
        {   // B1: 32 rows x N1, both planes
            constexpr int G8 = N1 / 8;
            #pragma unroll
            for (int it = 0; it < KC * G8 / 256; it++) {
                int idx = it * 256 + tid;
                int row = idx / G8, g = idx - row * G8;
                uint32_t dst = sbase + buf + ABUF + (uint32_t)(row * (SB1 * 2) + g * 16);
                cpa16(dst, (const char*)(B1h + (size_t)(c0 + row) * N1) + g * 16);
                cpa16(dst + SBB1, (const char*)(B1l + (size_t)(c0 + row) * N1) + g * 16);
            }
        }
        CP_COMMIT();
    };
    auto stage2 = [&](int c, uint32_t buf) {
        const int c0 = c * KC;
        constexpr int G8 = N2 / 8;
        #pragma unroll
        for (int it = 0; it < (KC * G8 + 255) / 256; it++) {
            int idx = it * 256 + tid;
            if (KC * G8 % 256 == 0 || idx < KC * G8) {
                int row = idx / G8, g = idx - row * G8;
                uint32_t dst = sbase + buf + (uint32_t)(row * (SB2 * 2) + g * 16);
                cpa16(dst, (const char*)(B2h + (size_t)(c0 + row) * N2) + g * 16);
                cpa16(dst + SBB2, (const char*)(B2l + (size_t)(c0 + row) * N2) + g * 16);
            }
        }
        CP_COMMIT();
    };

    // =========================== phase 1 ===========================
    {
        const int col0 = wn * WC1;
        float acc[2][NT1][4];
        #pragma unroll
        for (int mt = 0; mt < 2; mt++)
            #pragma unroll
            for (int j = 0; j < NT1; j++)
                #pragma unroll
                for (int q = 0; q < 4; q++) acc[mt][j][q] = 0.f;

        stage1(0, BUF0);
        for (int c = 0; c < NCH1; c++) {
            if (c + 1 < NCH1) {
                stage1(c + 1, (c + 1) & 1 ? BUF1 : BUF0);
                CP_WAIT1();
            } else {
                CP_WAIT0();
            }
            __syncthreads();

            const uint32_t buf = (c & 1) ? BUF1 : BUF0;
            #pragma unroll
            for (int kk = 0; kk < KC; kk += 16) {
                uint32_t ah[2][4], al[2][4];
                #pragma unroll
                for (int mt = 0; mt < 2; mt++) {
                    uint32_t ra = sbase + buf +
                        (uint32_t)((32 * wm + 16 * mt + lrow) * 80 + kk * 2 + lhalf * 16);
                    ldsm_x4(ah[mt], ra);
                    ldsm_x4(al[mt], ra + APL);
                }
                #pragma unroll
                for (int ng = 0; ng < NTG1; ng++) {
                    uint32_t rb = sbase + buf + ABUF +
                        (uint32_t)(((kk + lrow) * SB1 + col0 + ng * 16) * 2 + lhalf * 16);
                    uint32_t bh[4], bl[4];
                    ldsm_x4t(bh, rb);
                    ldsm_x4t(bl, rb + SBB1);
                    #pragma unroll
                    for (int mt = 0; mt < 2; mt++) {
                        mma_bf16(acc[mt][2 * ng],     ah[mt], bh[0], bh[1]);
                        mma_bf16(acc[mt][2 * ng],     ah[mt], bl[0], bl[1]);
                        mma_bf16(acc[mt][2 * ng],     al[mt], bh[0], bh[1]);
                        mma_bf16(acc[mt][2 * ng + 1], ah[mt], bh[2], bh[3]);
                        mma_bf16(acc[mt][2 * ng + 1], ah[mt], bl[2], bl[3]);
                        mma_bf16(acc[mt][2 * ng + 1], al[mt], bh[2], bh[3]);
                    }
                }
            }
            __syncthreads();   // buffer free for restage / epilogue aliasing
        }

        // overlap: issue phase2 chunk 0 stage (BUF0 region is dead now)
        stage2(0, P2B0);

        // epilogue -> h smem planes (relu + split); overwrites BUF1 region
        #pragma unroll
        for (int mt = 0; mt < 2; mt++) {
            int row0 = 32 * wm + 16 * mt + qr;
            #pragma unroll
            for (int j = 0; j < NT1; j++) {
                int col = col0 + 8 * j + qc;
                float b0 = __ldg(&bias1[col]), b1 = __ldg(&bias1[col + 1]);
                float v00 = fmaxf(acc[mt][j][0] + b0, 0.f);
                float v01 = fmaxf(acc[mt][j][1] + b1, 0.f);
                float v10 = fmaxf(acc[mt][j][2] + b0, 0.f);
                float v11 = fmaxf(acc[mt][j][3] + b1, 0.f);
                uint32_t hp, lp;
                uint32_t o0 = (uint32_t)((row0 * HST + col) * 2);
                split_pair(v00, v01, hp, lp);
                *(uint32_t*)(dsm + o0) = hp;
                *(uint32_t*)(dsm + HPL + o0) = lp;
                uint32_t o1 = o0 + (uint32_t)(8 * HST * 2);
                split_pair(v10, v11, hp, lp);
                *(uint32_t*)(dsm + o1) = hp;
                *(uint32_t*)(dsm + HPL + o1) = lp;
            }
        }
    }
    __syncthreads();

    // =========================== phase 2 ===========================
    {
        const int col0 = wn * WC2;
        float acc[2][NT2][4];
        #pragma unroll
        for (int mt = 0; mt < 2; mt++)
            #pragma unroll
            for (int j = 0; j < NT2; j++)
                #pragma unroll
                for (int q = 0; q < 4; q++) acc[mt][j][q] = 0.f;

        for (int c = 0; c < NCH2; c++) {
            if (c + 1 < NCH2) {
                stage2(c + 1, (c + 1) & 1 ? P2B1 : P2B0);
                CP_WAIT1();
            } else {
                CP_WAIT0();
            }
            __syncthreads();

            const uint32_t buf = (c & 1) ? P2B1 : P2B0;
            const int c0 = c * KC;
            #pragma unroll
            for (int kk = 0; kk < KC; kk += 16) {
                uint32_t ah[2][4], al[2][4];
                #pragma unroll
                for (int mt = 0; mt < 2; mt++) {
                    uint32_t ra = sbase +
                        (uint32_t)(((32 * wm + 16 * mt + lrow) * HST + c0 + kk) * 2 + lhalf * 16);
                    ldsm_x4(ah[mt], ra);
                    ldsm_x4(al[mt], ra + HPL);
                }
                #pragma unroll
                for (int ng = 0; ng < NTG2; ng++) {
                    uint32_t rb = sbase + buf +
                        (uint32_t)(((kk + lrow) * SB2 + col0 + ng * 16) * 2 + lhalf * 16);
                    uint32_t bh[4], bl[4];
                    ldsm_x4t(bh, rb);
                    ldsm_x4t(bl, rb + SBB2);
                    #pragma unroll
                    for (int mt = 0; mt < 2; mt++) {
                        mma_bf16(acc[mt][2 * ng],     ah[mt], bh[0], bh[1]);
                        mma_bf16(acc[mt][2 * ng],     ah[mt], bl[0], bl[1]);
                        mma_bf16(acc[mt][2 * ng],     al[mt], bh[0], bh[1]);
                        mma_bf16(acc[mt][2 * ng + 1], ah[mt], bh[2], bh[3]);
                        mma_bf16(acc[mt][2 * ng + 1], ah[mt], bl[2], bl[3]);
                        mma_bf16(acc[mt][2 * ng + 1], al[mt], bh[2], bh[3]);
                    }
                }
            }
            if (c + 1 < NCH2) __syncthreads();
        }

        // epilogue -> global fp32
        #pragma unroll
        for (int mt = 0; mt < 2; mt++) {
            int row0 = 32 * wm + 16 * mt + qr;
            int row1 = row0 + 8;
            #pragma unroll
            for (int j = 0; j < NT2; j++) {
                int col = col0 + 8 * j + qc;
                float b0 = __ldg(&bias2[col]), b1 = __ldg(&bias2[col + 1]);
                float v00 = acc[mt][j][0] + b0, v01 = acc[mt][j][1] + b1;
                float v10 = acc[mt][j][2] + b0, v11 = acc[mt][j][3] + b1;
                if (row0 < rem)
                    *(float2*)(Cf + (size_t)(n0 + row0) * N2 + col) = make_float2(v00, v01);
                if (row1 < rem)
                    *(float2*)(Cf + (size_t)(n0 + row1) * N2 + col) = make_float2(v10, v11);
            }
        }
    }
}

// ------------------------------- launcher ----------------------------------
extern "C" void kernel_launch(void* const* d_in, const int* in_sizes, int n_in,
                              void* d_out, int out_size) {
    const float* x   = (const float*)d_in[0];
    const int*   ei  = (const int*)d_in[1];
    const float* c1W = (const float*)d_in[2];
    const float* c1r = (const float*)d_in[3];
    const float* c1b = (const float*)d_in[4];
    const float* c2W = (const float*)d_in[5];
    const float* c2r = (const float*)d_in[6];
    const float* c2b = (const float*)d_in[7];
    const float* dw1 = (const float*)d_in[8];
    const float* db1 = (const float*)d_in[9];
    const float* dw2 = (const float*)d_in[10];
    const float* db2 = (const float*)d_in[11];
    float* out = (float*)d_out;

    void *pB2c, *pW;
    void *pA1h, *pA1l, *pZh, *pZl;
    void *pB1h, *pB1l, *pB2h, *pB2l, *pD1h, *pD1l, *pD2h, *pD2l;
    cudaGetSymbolAddress(&pB2c, g_b2c);
    cudaGetSymbolAddress(&pW, g_w);
    cudaGetSymbolAddress(&pA1h, g_A1h); cudaGetSymbolAddress(&pA1l, g_A1l);
    cudaGetSymbolAddress(&pZh, g_zh);   cudaGetSymbolAddress(&pZl, g_zl);
    cudaGetSymbolAddress(&pB1h, g_B1h); cudaGetSymbolAddress(&pB1l, g_B1l);
    cudaGetSymbolAddress(&pB2h, g_B2h); cudaGetSymbolAddress(&pB2l, g_B2l);
    cudaGetSymbolAddress(&pD1h, g_D1h); cudaGetSymbolAddress(&pD1l, g_D1l);
    cudaGetSymbolAddress(&pD2h, g_D2h); cudaGetSymbolAddress(&pD2l, g_D2l);

    // smem: h planes 67584 + stage buf0 (A 10240 + B 33792) = 111616 -> occ 2
    const int SM_F = 67584 + 10240 + 33792;
    cudaFuncSetAttribute(fused2_k<128, 256, 256, 128>,
                         cudaFuncAttributeMaxDynamicSharedMemorySize, SM_F);
    cudaFuncSetAttribute(fused2_k<64, 256, 256, 64>,
                         cudaFuncAttributeMaxDynamicSharedMemorySize, SM_F);

    const int nFG = (NNODES + 63) / 64;                 // 782
    const int nE4Blocks = (NEDGES / 4 + 255) / 256;     // 782
    const int nAggBlocks = (NNODES * 32 + 255) / 256;   // 6250

    // --- CSR build + weight prep (fused histogram/prep kernel) ---
    histprep_k<<<NHIST_BLK + NPREP_BLK, 256>>>(ei, c1W, c1r, c2W, c2r, c2b, dw1, dw2);
    scanm_k<<<NB_SCAN, 1024>>>();
    place_k<<<nE4Blocks, 256>>>(ei);

    // --- conv1 input aggregation ---
    agg1_k<<<nAggBlocks, 256>>>(x);

    // --- fused conv1 GEMM + conv2 weight GEMM: A1 -> h(smem) -> hWr (fp32) ---
    fused2_k<128, 256, 256, 128><<<nFG, 256, SM_F>>>(
        (const __nv_bfloat16*)pA1h, (const __nv_bfloat16*)pA1l,
        (const __nv_bfloat16*)pB1h, (const __nv_bfloat16*)pB1l, c1b,
        (const __nv_bfloat16*)pB2h, (const __nv_bfloat16*)pB2l, (const float*)pB2c,
        (float*)pW, NNODES);

    // --- conv2 aggregation -> z planes ---
    agg2_k<<<nAggBlocks, 256>>>();

    // --- fused decoder: z -> h2(smem) -> out ---
    fused2_k<64, 256, 256, 64><<<nFG, 256, SM_F>>>(
        (const __nv_bfloat16*)pZh, (const __nv_bfloat16*)pZl,
        (const __nv_bfloat16*)pD1h, (const __nv_bfloat16*)pD1l, db1,
        (const __nv_bfloat16*)pD2h, (const __nv_bfloat16*)pD2l, db2,
        out, NNODES);
}